// round 3
// baseline (speedup 1.0000x reference)
#include <cuda_runtime.h>
#include <math.h>

// ---------------- geometry ----------------
#define BB   2
#define LL   4096
#define DM   1024
#define DIN  2048
#define HH   32
#define PP   64
#define NSt  128
#define NCH  2304      // DIN + 2*NSt
#define NPJ  4384      // 2*DIN + 2*NSt + HH
#define CHK  256
#define NC   16        // chunks per batch
#define ROWS 8192      // BB*LL
#define NBC  32        // BB*NC
#define EPSF 1e-5f

// ---------------- scratch (static device memory, alloc-free) ----------------
__device__ float g_hn[(size_t)ROWS * DM];        // normalized input
__device__ float g_zx[(size_t)ROWS * NPJ];       // in_proj output
__device__ float g_xBC[(size_t)ROWS * NCH];      // conv+silu output (x | B | C)
__device__ float g_dt[ROWS * HH];                // softplus(dt)
__device__ float g_Acum[NBC * HH * CHK];         // per-chunk inclusive cumsum of dt*A
__device__ float g_S[(size_t)NBC * CHK * CHK];   // ST[s*256+l] per (b,c)
__device__ float g_states[(size_t)NBC * HH * PP * NSt];
__device__ float g_prev[(size_t)NBC * HH * PP * NSt];
__device__ float g_y[(size_t)ROWS * DIN];
__device__ float g_yn[(size_t)ROWS * DIN];

// ---------------- helpers ----------------
__device__ __forceinline__ float blockReduceSum256(float v) {
    __shared__ float red[32];
    int lane = threadIdx.x & 31, wid = threadIdx.x >> 5;
    #pragma unroll
    for (int o = 16; o; o >>= 1) v += __shfl_down_sync(0xffffffffu, v, o);
    if (lane == 0) red[wid] = v;
    __syncthreads();
    v = (threadIdx.x < 8) ? red[threadIdx.x] : 0.f;
    if (wid == 0) {
        #pragma unroll
        for (int o = 4; o; o >>= 1) v += __shfl_down_sync(0xffffffffu, v, o);
        if (lane == 0) red[0] = v;
    }
    __syncthreads();
    return red[0];
}

__device__ __forceinline__ float softplusf(float x) {
    return (x > 20.f) ? x : log1pf(expf(x));
}
__device__ __forceinline__ float siluf(float x) {
    return x / (1.f + expf(-x));
}

// ---------------- 1) residual add + RMSNorm ----------------
__global__ __launch_bounds__(256) void k_addnorm(
    const float* __restrict__ hid, const float* __restrict__ resi,
    const float* __restrict__ w, float* __restrict__ resout)
{
    int row = blockIdx.x, t = threadIdx.x;
    size_t off = (size_t)row * DM;
    float4 hv = ((const float4*)(hid + off))[t];
    float4 rv = ((const float4*)(resi + off))[t];
    hv.x += rv.x; hv.y += rv.y; hv.z += rv.z; hv.w += rv.w;
    ((float4*)(resout + off))[t] = hv;
    float s = hv.x*hv.x + hv.y*hv.y + hv.z*hv.z + hv.w*hv.w;
    s = blockReduceSum256(s);
    float sc = rsqrtf(s * (1.0f / DM) + EPSF);
    float4 wv = ((const float4*)w)[t];
    float4 o;
    o.x = hv.x * sc * wv.x; o.y = hv.y * sc * wv.y;
    o.z = hv.z * sc * wv.z; o.w = hv.w * sc * wv.w;
    ((float4*)(g_hn + off))[t] = o;
}

// ---------------- 2) SGEMM: C[M,N] = A[M,K] @ B[K,N] (row-major) ----------------
// 128x128x16 tile, 256 threads, 8x8 register tile. M%128==0, K%16==0, N%4==0.
__global__ __launch_bounds__(256) void sgemm(
    const float* __restrict__ A, const float* __restrict__ Bm,
    float* __restrict__ C, int M, int N, int K)
{
    __shared__ float As[16][128];
    __shared__ float Bs[16][128];
    int tid = threadIdx.x;
    int rowBase = blockIdx.y * 128, colBase = blockIdx.x * 128;
    int tx = tid & 15, ty = tid >> 4;
    int aRow = tid >> 2, aCol = (tid & 3) << 2;
    int bRow = tid >> 5, bCol = (tid & 31) << 2;
    float acc[8][8] = {};
    for (int k0 = 0; k0 < K; k0 += 16) {
        #pragma unroll
        for (int hh = 0; hh < 2; hh++) {
            int r = aRow + hh * 64;
            float4 v = *(const float4*)(A + (size_t)(rowBase + r) * K + k0 + aCol);
            As[aCol + 0][r] = v.x; As[aCol + 1][r] = v.y;
            As[aCol + 2][r] = v.z; As[aCol + 3][r] = v.w;
        }
        #pragma unroll
        for (int hh = 0; hh < 2; hh++) {
            int r = bRow + hh * 8;
            int cc = colBase + bCol;
            float4 v = make_float4(0.f, 0.f, 0.f, 0.f);
            if (cc < N) v = *(const float4*)(Bm + (size_t)(k0 + r) * N + cc);
            *(float4*)&Bs[r][bCol] = v;
        }
        __syncthreads();
        #pragma unroll
        for (int kk = 0; kk < 16; kk++) {
            float ar[8], br[8];
            *(float4*)&ar[0] = *(const float4*)&As[kk][ty * 8];
            *(float4*)&ar[4] = *(const float4*)&As[kk][ty * 8 + 4];
            *(float4*)&br[0] = *(const float4*)&Bs[kk][tx * 8];
            *(float4*)&br[4] = *(const float4*)&Bs[kk][tx * 8 + 4];
            #pragma unroll
            for (int i = 0; i < 8; i++)
                #pragma unroll
                for (int j = 0; j < 8; j++)
                    acc[i][j] += ar[i] * br[j];
        }
        __syncthreads();
    }
    #pragma unroll
    for (int i = 0; i < 8; i++) {
        int r = rowBase + ty * 8 + i;
        #pragma unroll
        for (int j4 = 0; j4 < 2; j4++) {
            int cc = colBase + tx * 8 + j4 * 4;
            if (cc < N) {
                float4 v = make_float4(acc[i][j4*4], acc[i][j4*4+1], acc[i][j4*4+2], acc[i][j4*4+3]);
                *(float4*)(C + (size_t)r * N + cc) = v;
            }
        }
    }
}

// ---------------- 3) depthwise causal conv (w=4) + bias + SiLU ----------------
__global__ __launch_bounds__(256) void k_conv(
    const float* __restrict__ cw, const float* __restrict__ cb)
{
    int ch = blockIdx.x * 256 + threadIdx.x;   // 0..2303
    int row = blockIdx.y;                      // 0..8191
    int b = row >> 12, l = row & 4095;
    float acc = cb[ch];
    #pragma unroll
    for (int w = 0; w < 4; w++) {
        int ls = l - 3 + w;
        if (ls >= 0)
            acc += g_zx[(size_t)(b * LL + ls) * NPJ + DIN + ch] * cw[w * NCH + ch];
    }
    g_xBC[(size_t)row * NCH + ch] = siluf(acc);
}

// ---------------- 4) dt = softplus(raw+bias); per-chunk cumsum of dt*A ----------------
__global__ __launch_bounds__(256) void k_dtscan(
    const float* __restrict__ dtb, const float* __restrict__ alog)
{
    int bc = blockIdx.x, h = blockIdx.y, l = threadIdx.x;
    int b = bc >> 4, c = bc & 15;
    int row = b * LL + c * CHK + l;
    float raw = g_zx[(size_t)row * NPJ + DIN + NCH + h] + dtb[h];
    float dt = softplusf(raw);
    g_dt[row * HH + h] = dt;
    float v = -dt * expf(alog[h]);
    __shared__ float sb[CHK];
    sb[l] = v;
    __syncthreads();
    for (int o = 1; o < CHK; o <<= 1) {
        float add = (l >= o) ? sb[l - o] : 0.f;
        __syncthreads();
        sb[l] += add;
        __syncthreads();
    }
    g_Acum[(bc * HH + h) * CHK + l] = sb[l];
}

// ---------------- 5) ST[s,l] = sum_n B[s,n]*C[l,n] per (b,c) ----------------
// grid (4 s-tiles, 4 l-tiles, 32 bc)
__global__ __launch_bounds__(256) void k_S()
{
    int st = blockIdx.x, lt = blockIdx.y, bc = blockIdx.z;
    int b = bc >> 4, c = bc & 15;
    int rowb = b * LL + c * CHK;
    int s0 = st * 64, l0 = lt * 64;
    __shared__ float Bsm[32][68];
    __shared__ float Csm[32][68];
    int t = threadIdx.x;
    int ts = t >> 4, tg = t & 15;
    float acc[4][4] = {};
    for (int kt = 0; kt < 4; kt++) {
        for (int idx = t; idx < 2048; idx += 256) {
            int n = idx & 31, s = idx >> 5;
            Bsm[n][s] = g_xBC[(size_t)(rowb + s0 + s) * NCH + DIN + kt * 32 + n];
            Csm[n][s] = g_xBC[(size_t)(rowb + l0 + s) * NCH + DIN + NSt + kt * 32 + n];
        }
        __syncthreads();
        #pragma unroll
        for (int n = 0; n < 32; n++) {
            float sv[4], lv[4];
            *(float4*)&sv[0] = *(const float4*)&Bsm[n][ts * 4];
            *(float4*)&lv[0] = *(const float4*)&Csm[n][tg * 4];
            #pragma unroll
            for (int i = 0; i < 4; i++)
                #pragma unroll
                for (int j = 0; j < 4; j++)
                    acc[i][j] += sv[i] * lv[j];
        }
        __syncthreads();
    }
    float* out = g_S + (size_t)bc * CHK * CHK;
    #pragma unroll
    for (int i = 0; i < 4; i++) {
        float4 v = make_float4(acc[i][0], acc[i][1], acc[i][2], acc[i][3]);
        *(float4*)&out[(s0 + ts * 4 + i) * CHK + l0 + tg * 4] = v;
    }
}

// ---------------- 6) states[p,n] = sum_l B[l,n]*exp(Alast-Acum[l])*x[l,p]*dt[l] ----------------
// grid (32 bc, 32 h)
__global__ __launch_bounds__(256) void k_states()
{
    int bc = blockIdx.x, h = blockIdx.y;
    int b = bc >> 4, c = bc & 15;
    int rowb = b * LL + c * CHK;
    const float* Ac = g_Acum + (bc * HH + h) * CHK;
    __shared__ float wsm[32];
    __shared__ float Bs[32][128];
    __shared__ float Xs[32][68];
    int t = threadIdx.x;
    int tn = t & 15, tp = t >> 4;
    float acc[4][8] = {};
    float alast = Ac[CHK - 1];
    for (int lt = 0; lt < 8; lt++) {
        if (t < 32) wsm[t] = expf(alast - Ac[lt * 32 + t]);
        __syncthreads();
        for (int idx = t; idx < 4096; idx += 256) {
            int n = idx & 127, ll = idx >> 7;
            Bs[ll][n] = g_xBC[(size_t)(rowb + lt * 32 + ll) * NCH + DIN + n] * wsm[ll];
        }
        for (int idx = t; idx < 2048; idx += 256) {
            int p = idx & 63, ll = idx >> 6;
            int row = rowb + lt * 32 + ll;
            Xs[ll][p] = g_xBC[(size_t)row * NCH + h * PP + p] * g_dt[row * HH + h];
        }
        __syncthreads();
        #pragma unroll
        for (int ll = 0; ll < 32; ll++) {
            float pr[4], nr[8];
            *(float4*)&pr[0] = *(const float4*)&Xs[ll][tp * 4];
            *(float4*)&nr[0] = *(const float4*)&Bs[ll][tn * 8];
            *(float4*)&nr[4] = *(const float4*)&Bs[ll][tn * 8 + 4];
            #pragma unroll
            for (int i = 0; i < 4; i++)
                #pragma unroll
                for (int j = 0; j < 8; j++)
                    acc[i][j] += pr[i] * nr[j];
        }
        __syncthreads();
    }
    float* out = g_states + (size_t)(bc * HH + h) * PP * NSt;
    #pragma unroll
    for (int i = 0; i < 4; i++) {
        int p = tp * 4 + i;
        *(float4*)&out[p * NSt + tn * 8]     = make_float4(acc[i][0], acc[i][1], acc[i][2], acc[i][3]);
        *(float4*)&out[p * NSt + tn * 8 + 4] = make_float4(acc[i][4], acc[i][5], acc[i][6], acc[i][7]);
    }
}

// ---------------- 7) inter-chunk recurrence ----------------
__global__ __launch_bounds__(256) void k_scan()
{
    int tid = blockIdx.x * 256 + threadIdx.x;  // 2*32*64*128 = 524288
    int n = tid & 127;
    int p = (tid >> 7) & 63;
    int h = (tid >> 13) & 31;
    int b = tid >> 18;
    float carry = 0.f;
    for (int c = 0; c < NC; c++) {
        int bc = b * NC + c;
        size_t idx = (size_t)(bc * HH + h) * PP * NSt + p * NSt + n;
        float dec = expf(g_Acum[(bc * HH + h) * CHK + CHK - 1]);
        g_prev[idx] = carry;
        carry = carry * dec + g_states[idx];
    }
}

// ---------------- 8) Y = Y_off + Y_diag + D*x ----------------
// grid (32 bc, 32 h); thread (tl = t>>2 owns 4 l, tp = t&3 owns 16 p)
__global__ __launch_bounds__(256) void k_Y(const float* __restrict__ Dp)
{
    int bc = blockIdx.x, h = blockIdx.y;
    int b = bc >> 4, c = bc & 15;
    int rowb = b * LL + c * CHK;
    int t = threadIdx.x;
    int tl = t >> 2, tp = t & 3;
    int l0 = tl * 4;

    __shared__ float Asm[CHK];
    __shared__ float buf[32 * 260 + 32 * 68];  // off: Csm|Psm ; diag: Xs (reused)
    float* Csm = buf;
    float* Psm = buf + 32 * 260;
    float* Xs  = buf;

    const float* Ac = g_Acum + (bc * HH + h) * CHK;
    Asm[t] = Ac[t];
    __syncthreads();
    float al[4];
    #pragma unroll
    for (int i = 0; i < 4; i++) al[i] = Asm[l0 + i];

    float acc[4][16] = {};
    const float* prevp = g_prev + (size_t)(bc * HH + h) * PP * NSt;

    // ---- Y_off: sum_n C[l,n]*prev[p,n], scaled by exp(Acum[l]) later ----
    for (int nt = 0; nt < 4; nt++) {
        for (int idx = t; idx < 8192; idx += 256) {
            int n = idx & 31, l = idx >> 5;
            Csm[n * 260 + l] = g_xBC[(size_t)(rowb + l) * NCH + DIN + NSt + nt * 32 + n];
        }
        for (int idx = t; idx < 2048; idx += 256) {
            int n = idx & 31, p = idx >> 5;
            Psm[n * 68 + p] = prevp[p * NSt + nt * 32 + n];
        }
        __syncthreads();
        #pragma unroll
        for (int n = 0; n < 32; n++) {
            float cl[4], pv[16];
            *(float4*)&cl[0] = *(const float4*)&Csm[n * 260 + l0];
            *(float4*)&pv[0]  = *(const float4*)&Psm[n * 68 + tp * 16];
            *(float4*)&pv[4]  = *(const float4*)&Psm[n * 68 + tp * 16 + 4];
            *(float4*)&pv[8]  = *(const float4*)&Psm[n * 68 + tp * 16 + 8];
            *(float4*)&pv[12] = *(const float4*)&Psm[n * 68 + tp * 16 + 12];
            #pragma unroll
            for (int i = 0; i < 4; i++)
                #pragma unroll
                for (int j = 0; j < 16; j++)
                    acc[i][j] += cl[i] * pv[j];
        }
        __syncthreads();
    }
    #pragma unroll
    for (int i = 0; i < 4; i++) {
        float el = expf(al[i]);
        #pragma unroll
        for (int j = 0; j < 16; j++) acc[i][j] *= el;
    }

    // ---- Y_diag: sum_{s<=l} ST[s,l]*exp(Acum[l]-Acum[s])*xdt[s,p] ----
    const float* Sp = g_S + (size_t)bc * CHK * CHK;
    for (int st = 0; st < 4; st++) {
        for (int idx = t; idx < 4096; idx += 256) {
            int p = idx & 63, ss = idx >> 6;
            int row = rowb + st * 64 + ss;
            Xs[ss * 68 + p] = g_xBC[(size_t)row * NCH + h * PP + p] * g_dt[row * HH + h];
        }
        __syncthreads();
        if (st * 64 <= l0 + 3) {
            int smax = min(64, l0 + 4 - st * 64);
            for (int ss = 0; ss < smax; ss++) {
                int s = st * 64 + ss;
                float as = Asm[s];
                float sv[4], w[4], xv[16];
                *(float4*)&sv[0] = *(const float4*)&Sp[s * CHK + l0];
                #pragma unroll
                for (int i = 0; i < 4; i++)
                    w[i] = (s <= l0 + i) ? sv[i] * expf(al[i] - as) : 0.f;
                *(float4*)&xv[0]  = *(const float4*)&Xs[ss * 68 + tp * 16];
                *(float4*)&xv[4]  = *(const float4*)&Xs[ss * 68 + tp * 16 + 4];
                *(float4*)&xv[8]  = *(const float4*)&Xs[ss * 68 + tp * 16 + 8];
                *(float4*)&xv[12] = *(const float4*)&Xs[ss * 68 + tp * 16 + 12];
                #pragma unroll
                for (int i = 0; i < 4; i++)
                    #pragma unroll
                    for (int j = 0; j < 16; j++)
                        acc[i][j] += w[i] * xv[j];
            }
        }
        __syncthreads();
    }

    // ---- skip term + store ----
    float dh = Dp[h];
    #pragma unroll
    for (int i = 0; i < 4; i++) {
        int row = rowb + l0 + i;
        const float* xr = g_xBC + (size_t)row * NCH + h * PP + tp * 16;
        float* yr = g_y + (size_t)row * DIN + h * PP + tp * 16;
        #pragma unroll
        for (int j4 = 0; j4 < 4; j4++) {
            float4 xv = *(const float4*)(xr + j4 * 4);
            float4 o;
            o.x = acc[i][j4 * 4 + 0] + dh * xv.x;
            o.y = acc[i][j4 * 4 + 1] + dh * xv.y;
            o.z = acc[i][j4 * 4 + 2] + dh * xv.z;
            o.w = acc[i][j4 * 4 + 3] + dh * xv.w;
            *(float4*)(yr + j4 * 4) = o;
        }
    }
}

// ---------------- 9) gated SiLU + RMSNorm over 2048 ----------------
__global__ __launch_bounds__(256) void k_gatednorm(const float* __restrict__ gw)
{
    int row = blockIdx.x, t = threadIdx.x;
    size_t yo = (size_t)row * DIN;
    size_t zo = (size_t)row * NPJ;
    float4 vv[2];
    float ssum = 0.f;
    #pragma unroll
    for (int k = 0; k < 2; k++) {
        float4 yv = ((const float4*)(g_y + yo))[k * 256 + t];
        float4 zv = ((const float4*)(g_zx + zo))[k * 256 + t];
        float4 v;
        v.x = yv.x * siluf(zv.x); v.y = yv.y * siluf(zv.y);
        v.z = yv.z * siluf(zv.z); v.w = yv.w * siluf(zv.w);
        vv[k] = v;
        ssum += v.x * v.x + v.y * v.y + v.z * v.z + v.w * v.w;
    }
    ssum = blockReduceSum256(ssum);
    float sc = rsqrtf(ssum * (1.0f / DIN) + EPSF);
    #pragma unroll
    for (int k = 0; k < 2; k++) {
        float4 w = ((const float4*)gw)[k * 256 + t];
        float4 v = vv[k];
        float4 o;
        o.x = v.x * sc * w.x; o.y = v.y * sc * w.y;
        o.z = v.z * sc * w.z; o.w = v.w * sc * w.w;
        ((float4*)(g_yn + yo))[k * 256 + t] = o;
    }
}

// ---------------- launch ----------------
extern "C" void kernel_launch(void* const* d_in, const int* in_sizes, int n_in,
                              void* d_out, int out_size)
{
    const float* hid  = (const float*)d_in[0];
    const float* resi = (const float*)d_in[1];
    const float* nw   = (const float*)d_in[2];
    const float* inw  = (const float*)d_in[3];
    const float* cw   = (const float*)d_in[4];
    const float* cb   = (const float*)d_in[5];
    const float* dtb  = (const float*)d_in[6];
    const float* alog = (const float*)d_in[7];
    const float* Dp   = (const float*)d_in[8];
    const float* gw   = (const float*)d_in[9];
    const float* ow   = (const float*)d_in[10];

    float* out    = (float*)d_out;
    float* resout = out + (size_t)ROWS * DM;

    float *p_hn, *p_zx, *p_yn;
    cudaGetSymbolAddress((void**)&p_hn, g_hn);
    cudaGetSymbolAddress((void**)&p_zx, g_zx);
    cudaGetSymbolAddress((void**)&p_yn, g_yn);

    k_addnorm<<<ROWS, 256>>>(hid, resi, nw, resout);
    sgemm<<<dim3((NPJ + 127) / 128, ROWS / 128), 256>>>(p_hn, inw, p_zx, ROWS, NPJ, DM);
    k_conv<<<dim3(NCH / 256, ROWS), 256>>>(cw, cb);
    k_dtscan<<<dim3(NBC, HH), 256>>>(dtb, alog);
    k_S<<<dim3(4, 4, NBC), 256>>>();
    k_states<<<dim3(NBC, HH), 256>>>();
    k_scan<<<(BB * HH * PP * NSt) / 256, 256>>>();
    k_Y<<<dim3(NBC, HH), 256>>>(Dp);
    k_gatednorm<<<ROWS, 256>>>(gw);
    sgemm<<<dim3(DM / 128, ROWS / 128), 256>>>(p_yn, ow, out, ROWS, DM, DIN);
}

// round 4
// speedup vs baseline: 1.9495x; 1.9495x over previous
#include <cuda_runtime.h>
#include <math.h>

// ---------------- geometry ----------------
#define BB   2
#define LL   4096
#define DM   1024
#define DIN  2048
#define HH   32
#define PP   64
#define NSt  128
#define NCH  2304      // DIN + 2*NSt
#define NPJ  4384      // 2*DIN + 2*NSt + HH
#define CHK  256
#define NC   16        // chunks per batch
#define ROWS 8192      // BB*LL
#define NBC  32        // BB*NC
#define EPSF 1e-5f

// ---------------- scratch (static device memory, alloc-free) ----------------
__device__ float g_hn[(size_t)ROWS * DM];        // normalized input
__device__ float g_zx[(size_t)ROWS * NPJ];       // in_proj output
__device__ float g_xBC[(size_t)ROWS * NCH];      // conv+silu output (x | B | C)
__device__ float g_dt[ROWS * HH];                // softplus(dt)
__device__ float g_Acum[NBC * HH * CHK];         // per-chunk inclusive cumsum of dt*A
__device__ float g_cdec[NBC * HH];               // exp(Acum[last]) per (bc,h)
__device__ float g_S[(size_t)NBC * CHK * CHK];   // ST[s*256+l] per (b,c)
__device__ float g_states[(size_t)NBC * HH * PP * NSt];
__device__ float g_prev[(size_t)NBC * HH * PP * NSt];
__device__ float g_y[(size_t)ROWS * DIN];
__device__ float g_yn[(size_t)ROWS * DIN];

// ---------------- helpers ----------------
__device__ __forceinline__ float blockReduceSum256(float v) {
    __shared__ float red[32];
    int lane = threadIdx.x & 31, wid = threadIdx.x >> 5;
    #pragma unroll
    for (int o = 16; o; o >>= 1) v += __shfl_down_sync(0xffffffffu, v, o);
    if (lane == 0) red[wid] = v;
    __syncthreads();
    v = (threadIdx.x < 8) ? red[threadIdx.x] : 0.f;
    if (wid == 0) {
        #pragma unroll
        for (int o = 4; o; o >>= 1) v += __shfl_down_sync(0xffffffffu, v, o);
        if (lane == 0) red[0] = v;
    }
    __syncthreads();
    return red[0];
}

__device__ __forceinline__ float softplusf(float x) {
    return (x > 20.f) ? x : log1pf(expf(x));
}
__device__ __forceinline__ float siluf(float x) {
    return x / (1.f + expf(-x));
}
__device__ __forceinline__ unsigned f2tf(float f) {
    unsigned u;
    asm("cvt.rna.tf32.f32 %0, %1;" : "=r"(u) : "f"(f));
    return u;
}
__device__ __forceinline__ void mma_tf32(float* d, const unsigned* a, const unsigned* b) {
    asm volatile(
        "mma.sync.aligned.m16n8k8.row.col.f32.tf32.tf32.f32 "
        "{%0,%1,%2,%3}, {%4,%5,%6,%7}, {%8,%9}, {%0,%1,%2,%3};"
        : "+f"(d[0]), "+f"(d[1]), "+f"(d[2]), "+f"(d[3])
        : "r"(a[0]), "r"(a[1]), "r"(a[2]), "r"(a[3]), "r"(b[0]), "r"(b[1]));
}

// ---------------- 1) residual add + RMSNorm ----------------
__global__ __launch_bounds__(256) void k_addnorm(
    const float* __restrict__ hid, const float* __restrict__ resi,
    const float* __restrict__ w, float* __restrict__ resout)
{
    int row = blockIdx.x, t = threadIdx.x;
    size_t off = (size_t)row * DM;
    float4 hv = ((const float4*)(hid + off))[t];
    float4 rv = ((const float4*)(resi + off))[t];
    hv.x += rv.x; hv.y += rv.y; hv.z += rv.z; hv.w += rv.w;
    ((float4*)(resout + off))[t] = hv;
    float s = hv.x*hv.x + hv.y*hv.y + hv.z*hv.z + hv.w*hv.w;
    s = blockReduceSum256(s);
    float sc = rsqrtf(s * (1.0f / DM) + EPSF);
    float4 wv = ((const float4*)w)[t];
    float4 o;
    o.x = hv.x * sc * wv.x; o.y = hv.y * sc * wv.y;
    o.z = hv.z * sc * wv.z; o.w = hv.w * sc * wv.w;
    ((float4*)(g_hn + off))[t] = o;
}

// ---------------- 2) TF32 tensor-core GEMM: C[M,N] = A[M,K] @ B[K,N] ----------------
// 128x128x16 CTA tile, 256 threads = 8 warps (2x4), warp tile 64x32.
// A frags: ldmatrix.x4 from As[m][k] (stride 20, conflict-free).
// B frags: LDS.32 from Bs[k][n ^ ((k&3)<<3)] (conflict-free swizzle).
__global__ __launch_bounds__(256, 2) void gemm_tf32(
    const float* __restrict__ A, const float* __restrict__ Bm,
    float* __restrict__ C, int M, int N, int K)
{
    __shared__ unsigned As[128 * 20];
    __shared__ unsigned Bs[16 * 128];
    int tid = threadIdx.x;
    int lane = tid & 31, warp = tid >> 5;
    int warpRow = warp >> 2, warpCol = warp & 3;
    int rowBase = blockIdx.y * 128, colBase = blockIdx.x * 128;

    int aRow = tid >> 2, aCol = (tid & 3) << 2;
    int bRow = warp;                 // 0..7, uniform per warp
    int bCol = lane << 2;            // 0..124
    int gid = lane >> 2, tig = lane & 3;

    // ldmatrix per-lane address components
    int lm_row = lane & 15;
    int lm_koff = (lane >> 4) << 2;
    unsigned as_base = (unsigned)__cvta_generic_to_shared(As);

    float acc[4][4][4] = {};

    for (int k0 = 0; k0 < K; k0 += 16) {
        // stage A (rows aRow, aRow+64)
        #pragma unroll
        for (int hh = 0; hh < 2; hh++) {
            int r = aRow + hh * 64;
            float4 v = *(const float4*)(A + (size_t)(rowBase + r) * K + k0 + aCol);
            uint4 u = make_uint4(f2tf(v.x), f2tf(v.y), f2tf(v.z), f2tf(v.w));
            *(uint4*)&As[r * 20 + aCol] = u;
        }
        // stage B (rows bRow, bRow+8), swizzled columns
        #pragma unroll
        for (int hh = 0; hh < 2; hh++) {
            int r = bRow + hh * 8;
            int cc = colBase + bCol;
            float4 v = make_float4(0.f, 0.f, 0.f, 0.f);
            if (cc < N) v = *(const float4*)(Bm + (size_t)(k0 + r) * N + cc);
            uint4 u = make_uint4(f2tf(v.x), f2tf(v.y), f2tf(v.z), f2tf(v.w));
            *(uint4*)&Bs[r * 128 + (bCol ^ ((r & 3) << 3))] = u;
        }
        __syncthreads();

        #pragma unroll
        for (int ks = 0; ks < 2; ks++) {
            unsigned a[4][4], b[4][2];
            #pragma unroll
            for (int i = 0; i < 4; i++) {
                int mr = warpRow * 64 + i * 16;
                unsigned addr = as_base + (unsigned)(((mr + lm_row) * 20 + ks * 8 + lm_koff) << 2);
                asm volatile("ldmatrix.sync.aligned.m8n8.x4.shared.b16 {%0,%1,%2,%3}, [%4];"
                    : "=r"(a[i][0]), "=r"(a[i][1]), "=r"(a[i][2]), "=r"(a[i][3])
                    : "r"(addr));
            }
            #pragma unroll
            for (int j = 0; j < 4; j++) {
                int col = ((warpCol * 32 + j * 8 + gid) ^ (tig << 3));
                b[j][0] = Bs[(ks * 8 + tig) * 128 + col];
                b[j][1] = Bs[(ks * 8 + tig + 4) * 128 + col];
            }
            #pragma unroll
            for (int i = 0; i < 4; i++)
                #pragma unroll
                for (int j = 0; j < 4; j++)
                    mma_tf32(acc[i][j], a[i], b[j]);
        }
        __syncthreads();
    }

    // epilogue: c0,c1 at (r0, 2*tig), c2,c3 at (r0+8, 2*tig)
    #pragma unroll
    for (int i = 0; i < 4; i++) {
        int r0 = rowBase + warpRow * 64 + i * 16 + gid;
        #pragma unroll
        for (int j = 0; j < 4; j++) {
            int cc = colBase + warpCol * 32 + j * 8 + tig * 2;
            if (cc < N) {
                *(float2*)(C + (size_t)r0 * N + cc)       = make_float2(acc[i][j][0], acc[i][j][1]);
                *(float2*)(C + (size_t)(r0 + 8) * N + cc) = make_float2(acc[i][j][2], acc[i][j][3]);
            }
        }
    }
}

// ---------------- 3) depthwise causal conv (w=4) + bias + SiLU ----------------
__global__ __launch_bounds__(256) void k_conv(
    const float* __restrict__ cw, const float* __restrict__ cb)
{
    int ch = blockIdx.x * 256 + threadIdx.x;   // 0..2303
    int row = blockIdx.y;                      // 0..8191
    int b = row >> 12, l = row & 4095;
    float acc = cb[ch];
    #pragma unroll
    for (int w = 0; w < 4; w++) {
        int ls = l - 3 + w;
        if (ls >= 0)
            acc += g_zx[(size_t)(b * LL + ls) * NPJ + DIN + ch] * cw[w * NCH + ch];
    }
    g_xBC[(size_t)row * NCH + ch] = siluf(acc);
}

// ---------------- 4) dt = softplus(raw+bias); per-chunk cumsum of dt*A ----------------
__global__ __launch_bounds__(256) void k_dtscan(
    const float* __restrict__ dtb, const float* __restrict__ alog)
{
    int bc = blockIdx.x, h = blockIdx.y, l = threadIdx.x;
    int b = bc >> 4, c = bc & 15;
    int row = b * LL + c * CHK + l;
    float raw = g_zx[(size_t)row * NPJ + DIN + NCH + h] + dtb[h];
    float dt = softplusf(raw);
    g_dt[row * HH + h] = dt;
    float v = -dt * expf(alog[h]);
    __shared__ float sb[CHK];
    sb[l] = v;
    __syncthreads();
    for (int o = 1; o < CHK; o <<= 1) {
        float add = (l >= o) ? sb[l - o] : 0.f;
        __syncthreads();
        sb[l] += add;
        __syncthreads();
    }
    g_Acum[(bc * HH + h) * CHK + l] = sb[l];
    if (l == CHK - 1) g_cdec[bc * HH + h] = expf(sb[l]);
}

// ---------------- 5) ST[s,l] = sum_n B[s,n]*C[l,n] per (b,c) ----------------
__global__ __launch_bounds__(256) void k_S()
{
    int st = blockIdx.x, lt = blockIdx.y, bc = blockIdx.z;
    int b = bc >> 4, c = bc & 15;
    int rowb = b * LL + c * CHK;
    int s0 = st * 64, l0 = lt * 64;
    __shared__ float Bsm[32][68];
    __shared__ float Csm[32][68];
    int t = threadIdx.x;
    int ts = t >> 4, tg = t & 15;
    float acc[4][4] = {};
    for (int kt = 0; kt < 4; kt++) {
        for (int idx = t; idx < 2048; idx += 256) {
            int n = idx & 31, s = idx >> 5;
            Bsm[n][s] = g_xBC[(size_t)(rowb + s0 + s) * NCH + DIN + kt * 32 + n];
            Csm[n][s] = g_xBC[(size_t)(rowb + l0 + s) * NCH + DIN + NSt + kt * 32 + n];
        }
        __syncthreads();
        #pragma unroll
        for (int n = 0; n < 32; n++) {
            float sv[4], lv[4];
            *(float4*)&sv[0] = *(const float4*)&Bsm[n][ts * 4];
            *(float4*)&lv[0] = *(const float4*)&Csm[n][tg * 4];
            #pragma unroll
            for (int i = 0; i < 4; i++)
                #pragma unroll
                for (int j = 0; j < 4; j++)
                    acc[i][j] += sv[i] * lv[j];
        }
        __syncthreads();
    }
    float* out = g_S + (size_t)bc * CHK * CHK;
    #pragma unroll
    for (int i = 0; i < 4; i++) {
        float4 v = make_float4(acc[i][0], acc[i][1], acc[i][2], acc[i][3]);
        *(float4*)&out[(s0 + ts * 4 + i) * CHK + l0 + tg * 4] = v;
    }
}

// ---------------- 6) states[p,n] = sum_l B[l,n]*exp(Alast-Acum[l])*x[l,p]*dt[l] ----------------
__global__ __launch_bounds__(256) void k_states()
{
    int bc = blockIdx.x, h = blockIdx.y;
    int b = bc >> 4, c = bc & 15;
    int rowb = b * LL + c * CHK;
    const float* Ac = g_Acum + (bc * HH + h) * CHK;
    __shared__ float wsm[32];
    __shared__ float Bs[32][128];
    __shared__ float Xs[32][68];
    int t = threadIdx.x;
    int tn = t & 15, tp = t >> 4;
    float acc[4][8] = {};
    float alast = Ac[CHK - 1];
    for (int lt = 0; lt < 8; lt++) {
        if (t < 32) wsm[t] = expf(alast - Ac[lt * 32 + t]);
        __syncthreads();
        for (int idx = t; idx < 4096; idx += 256) {
            int n = idx & 127, ll = idx >> 7;
            Bs[ll][n] = g_xBC[(size_t)(rowb + lt * 32 + ll) * NCH + DIN + n] * wsm[ll];
        }
        for (int idx = t; idx < 2048; idx += 256) {
            int p = idx & 63, ll = idx >> 6;
            int row = rowb + lt * 32 + ll;
            Xs[ll][p] = g_xBC[(size_t)row * NCH + h * PP + p] * g_dt[row * HH + h];
        }
        __syncthreads();
        #pragma unroll
        for (int ll = 0; ll < 32; ll++) {
            float pr[4], nr[8];
            *(float4*)&pr[0] = *(const float4*)&Xs[ll][tp * 4];
            *(float4*)&nr[0] = *(const float4*)&Bs[ll][tn * 8];
            *(float4*)&nr[4] = *(const float4*)&Bs[ll][tn * 8 + 4];
            #pragma unroll
            for (int i = 0; i < 4; i++)
                #pragma unroll
                for (int j = 0; j < 8; j++)
                    acc[i][j] += pr[i] * nr[j];
        }
        __syncthreads();
    }
    float* out = g_states + (size_t)(bc * HH + h) * PP * NSt;
    #pragma unroll
    for (int i = 0; i < 4; i++) {
        int p = tp * 4 + i;
        *(float4*)&out[p * NSt + tn * 8]     = make_float4(acc[i][0], acc[i][1], acc[i][2], acc[i][3]);
        *(float4*)&out[p * NSt + tn * 8 + 4] = make_float4(acc[i][4], acc[i][5], acc[i][6], acc[i][7]);
    }
}

// ---------------- 7) inter-chunk recurrence ----------------
__global__ __launch_bounds__(256) void k_scan()
{
    int tid = blockIdx.x * 256 + threadIdx.x;  // 524288
    int n = tid & 127;
    int p = (tid >> 7) & 63;
    int h = (tid >> 13) & 31;
    int b = tid >> 18;
    float carry = 0.f;
    for (int c = 0; c < NC; c++) {
        int bc = b * NC + c;
        size_t idx = (size_t)(bc * HH + h) * PP * NSt + p * NSt + n;
        float dec = g_cdec[bc * HH + h];
        g_prev[idx] = carry;
        carry = carry * dec + g_states[idx];
    }
}

// ---------------- 8) Y = Y_off + Y_diag + D*x ----------------
__global__ __launch_bounds__(256) void k_Y(const float* __restrict__ Dp)
{
    int bc = blockIdx.x, h = blockIdx.y;
    int b = bc >> 4, c = bc & 15;
    int rowb = b * LL + c * CHK;
    int t = threadIdx.x;
    int tl = t >> 2, tp = t & 3;
    int l0 = tl * 4;

    __shared__ float Asm[CHK];
    __shared__ float buf[32 * 260 + 32 * 68];
    float* Csm = buf;
    float* Psm = buf + 32 * 260;
    float* Xs  = buf;

    const float* Ac = g_Acum + (bc * HH + h) * CHK;
    Asm[t] = Ac[t];
    __syncthreads();
    float al[4];
    #pragma unroll
    for (int i = 0; i < 4; i++) al[i] = Asm[l0 + i];
    // per-thread intra ratios: rr[i] = exp(al[i]-al[0]) (exponent <= 0, safe)
    float rr[4];
    rr[0] = 1.f;
    #pragma unroll
    for (int i = 1; i < 4; i++) rr[i] = expf(al[i] - al[0]);

    float acc[4][16] = {};
    const float* prevp = g_prev + (size_t)(bc * HH + h) * PP * NSt;

    // ---- Y_off ----
    for (int nt = 0; nt < 4; nt++) {
        for (int idx = t; idx < 8192; idx += 256) {
            int n = idx & 31, l = idx >> 5;
            Csm[n * 260 + l] = g_xBC[(size_t)(rowb + l) * NCH + DIN + NSt + nt * 32 + n];
        }
        for (int idx = t; idx < 2048; idx += 256) {
            int n = idx & 31, p = idx >> 5;
            Psm[n * 68 + p] = prevp[p * NSt + nt * 32 + n];
        }
        __syncthreads();
        #pragma unroll
        for (int n = 0; n < 32; n++) {
            float cl[4], pv[16];
            *(float4*)&cl[0] = *(const float4*)&Csm[n * 260 + l0];
            *(float4*)&pv[0]  = *(const float4*)&Psm[n * 68 + tp * 16];
            *(float4*)&pv[4]  = *(const float4*)&Psm[n * 68 + tp * 16 + 4];
            *(float4*)&pv[8]  = *(const float4*)&Psm[n * 68 + tp * 16 + 8];
            *(float4*)&pv[12] = *(const float4*)&Psm[n * 68 + tp * 16 + 12];
            #pragma unroll
            for (int i = 0; i < 4; i++)
                #pragma unroll
                for (int j = 0; j < 16; j++)
                    acc[i][j] += cl[i] * pv[j];
        }
        __syncthreads();
    }
    #pragma unroll
    for (int i = 0; i < 4; i++) {
        float el = expf(al[i]);
        #pragma unroll
        for (int j = 0; j < 16; j++) acc[i][j] *= el;
    }

    // ---- Y_diag: sum_{s<=l} ST[s,l]*exp(Acum[l]-Acum[s])*xdt[s,p] ----
    const float* Sp = g_S + (size_t)bc * CHK * CHK;
    for (int st = 0; st < 4; st++) {
        for (int idx = t; idx < 4096; idx += 256) {
            int p = idx & 63, ss = idx >> 6;
            int row = rowb + st * 64 + ss;
            Xs[ss * 68 + p] = g_xBC[(size_t)row * NCH + h * PP + p] * g_dt[row * HH + h];
        }
        __syncthreads();
        int sEnd = l0 + 1 - st * 64;  // fully-causal region: s <= l0
        if (sEnd > 64) sEnd = 64;
        int bEnd = l0 + 4 - st * 64;  // ragged region end: s <= l0+3
        if (bEnd > 64) bEnd = 64;
        // main region: one expf per (thread, s)
        for (int ss = 0; ss < sEnd; ss++) {
            int s = st * 64 + ss;
            float e0 = expf(al[0] - Asm[s]);     // <= 0 exponent, safe
            float sv[4], w[4], xv[16];
            *(float4*)&sv[0] = *(const float4*)&Sp[s * CHK + l0];
            #pragma unroll
            for (int i = 0; i < 4; i++) w[i] = sv[i] * (e0 * rr[i]);
            *(float4*)&xv[0]  = *(const float4*)&Xs[ss * 68 + tp * 16];
            *(float4*)&xv[4]  = *(const float4*)&Xs[ss * 68 + tp * 16 + 4];
            *(float4*)&xv[8]  = *(const float4*)&Xs[ss * 68 + tp * 16 + 8];
            *(float4*)&xv[12] = *(const float4*)&Xs[ss * 68 + tp * 16 + 12];
            #pragma unroll
            for (int i = 0; i < 4; i++)
                #pragma unroll
                for (int j = 0; j < 16; j++)
                    acc[i][j] += w[i] * xv[j];
        }
        // ragged boundary: l0 < s <= l0+3
        for (int ss = (sEnd > 0 ? sEnd : 0); ss < bEnd; ss++) {
            int s = st * 64 + ss;
            float as = Asm[s];
            float sv[4], w[4], xv[16];
            *(float4*)&sv[0] = *(const float4*)&Sp[s * CHK + l0];
            #pragma unroll
            for (int i = 0; i < 4; i++)
                w[i] = (s <= l0 + i) ? sv[i] * expf(al[i] - as) : 0.f;
            *(float4*)&xv[0]  = *(const float4*)&Xs[ss * 68 + tp * 16];
            *(float4*)&xv[4]  = *(const float4*)&Xs[ss * 68 + tp * 16 + 4];
            *(float4*)&xv[8]  = *(const float4*)&Xs[ss * 68 + tp * 16 + 8];
            *(float4*)&xv[12] = *(const float4*)&Xs[ss * 68 + tp * 16 + 12];
            #pragma unroll
            for (int i = 0; i < 4; i++)
                #pragma unroll
                for (int j = 0; j < 16; j++)
                    acc[i][j] += w[i] * xv[j];
        }
        __syncthreads();
    }

    // ---- skip term + store ----
    float dh = Dp[h];
    #pragma unroll
    for (int i = 0; i < 4; i++) {
        int row = rowb + l0 + i;
        const float* xr = g_xBC + (size_t)row * NCH + h * PP + tp * 16;
        float* yr = g_y + (size_t)row * DIN + h * PP + tp * 16;
        #pragma unroll
        for (int j4 = 0; j4 < 4; j4++) {
            float4 xv = *(const float4*)(xr + j4 * 4);
            float4 o;
            o.x = acc[i][j4 * 4 + 0] + dh * xv.x;
            o.y = acc[i][j4 * 4 + 1] + dh * xv.y;
            o.z = acc[i][j4 * 4 + 2] + dh * xv.z;
            o.w = acc[i][j4 * 4 + 3] + dh * xv.w;
            *(float4*)(yr + j4 * 4) = o;
        }
    }
}

// ---------------- 9) gated SiLU + RMSNorm over 2048 ----------------
__global__ __launch_bounds__(256) void k_gatednorm(const float* __restrict__ gw)
{
    int row = blockIdx.x, t = threadIdx.x;
    size_t yo = (size_t)row * DIN;
    size_t zo = (size_t)row * NPJ;
    float4 vv[2];
    float ssum = 0.f;
    #pragma unroll
    for (int k = 0; k < 2; k++) {
        float4 yv = ((const float4*)(g_y + yo))[k * 256 + t];
        float4 zv = ((const float4*)(g_zx + zo))[k * 256 + t];
        float4 v;
        v.x = yv.x * siluf(zv.x); v.y = yv.y * siluf(zv.y);
        v.z = yv.z * siluf(zv.z); v.w = yv.w * siluf(zv.w);
        vv[k] = v;
        ssum += v.x * v.x + v.y * v.y + v.z * v.z + v.w * v.w;
    }
    ssum = blockReduceSum256(ssum);
    float sc = rsqrtf(ssum * (1.0f / DIN) + EPSF);
    #pragma unroll
    for (int k = 0; k < 2; k++) {
        float4 w = ((const float4*)gw)[k * 256 + t];
        float4 v = vv[k];
        float4 o;
        o.x = v.x * sc * w.x; o.y = v.y * sc * w.y;
        o.z = v.z * sc * w.z; o.w = v.w * sc * w.w;
        ((float4*)(g_yn + yo))[k * 256 + t] = o;
    }
}

// ---------------- launch ----------------
extern "C" void kernel_launch(void* const* d_in, const int* in_sizes, int n_in,
                              void* d_out, int out_size)
{
    const float* hid  = (const float*)d_in[0];
    const float* resi = (const float*)d_in[1];
    const float* nw   = (const float*)d_in[2];
    const float* inw  = (const float*)d_in[3];
    const float* cw   = (const float*)d_in[4];
    const float* cb   = (const float*)d_in[5];
    const float* dtb  = (const float*)d_in[6];
    const float* alog = (const float*)d_in[7];
    const float* Dp   = (const float*)d_in[8];
    const float* gw   = (const float*)d_in[9];
    const float* ow   = (const float*)d_in[10];

    float* out    = (float*)d_out;
    float* resout = out + (size_t)ROWS * DM;

    float *p_hn, *p_zx, *p_yn;
    cudaGetSymbolAddress((void**)&p_hn, g_hn);
    cudaGetSymbolAddress((void**)&p_zx, g_zx);
    cudaGetSymbolAddress((void**)&p_yn, g_yn);

    k_addnorm<<<ROWS, 256>>>(hid, resi, nw, resout);
    gemm_tf32<<<dim3((NPJ + 127) / 128, ROWS / 128), 256>>>(p_hn, inw, p_zx, ROWS, NPJ, DM);
    k_conv<<<dim3(NCH / 256, ROWS), 256>>>(cw, cb);
    k_dtscan<<<dim3(NBC, HH), 256>>>(dtb, alog);
    k_S<<<dim3(4, 4, NBC), 256>>>();
    k_states<<<dim3(NBC, HH), 256>>>();
    k_scan<<<(BB * HH * PP * NSt) / 256, 256>>>();
    k_Y<<<dim3(NBC, HH), 256>>>(Dp);
    k_gatednorm<<<ROWS, 256>>>(gw);
    gemm_tf32<<<dim3(DM / 128, ROWS / 128), 256>>>(p_yn, ow, out, ROWS, DM, DIN);
}

// round 5
// speedup vs baseline: 2.2489x; 1.1536x over previous
#include <cuda_runtime.h>
#include <math.h>

// ---------------- geometry ----------------
#define BB   2
#define LL   4096
#define DM   1024
#define DIN  2048
#define HH   32
#define PP   64
#define NSt  128
#define NCH  2304      // DIN + 2*NSt
#define NPJ  4384      // 2*DIN + 2*NSt + HH
#define CHK  256
#define NC   16        // chunks per batch
#define ROWS 8192      // BB*LL
#define NBC  32        // BB*NC
#define EPSF 1e-5f

// ---------------- scratch (static device memory, alloc-free) ----------------
__device__ float g_hn[(size_t)ROWS * DM];        // normalized input (tf32-rounded)
__device__ float g_zx[(size_t)ROWS * NPJ];       // in_proj output
__device__ float g_xBC[(size_t)ROWS * NCH];      // conv+silu output (x | B | C)
__device__ float g_dt[ROWS * HH];                // softplus(dt)
__device__ float g_Acum[NBC * HH * CHK];         // per-chunk inclusive cumsum of dt*A
__device__ float g_cdec[NBC * HH];               // exp(Acum[last]) per (bc,h)
__device__ float g_S[(size_t)NBC * CHK * CHK];   // ST[s*256+l] per (b,c)
__device__ float g_states[(size_t)NBC * HH * PP * NSt];
__device__ float g_prev[(size_t)NBC * HH * PP * NSt];
__device__ float g_y[(size_t)ROWS * DIN];
__device__ float g_yn[(size_t)ROWS * DIN];       // (tf32-rounded)
__device__ float g_w1[(size_t)DM * NPJ];         // tf32-rounded in_proj_w
__device__ float g_w2[(size_t)DIN * DM];         // tf32-rounded out_proj_w

// ---------------- helpers ----------------
__device__ __forceinline__ float blockReduceSum256(float v) {
    __shared__ float red[32];
    int lane = threadIdx.x & 31, wid = threadIdx.x >> 5;
    #pragma unroll
    for (int o = 16; o; o >>= 1) v += __shfl_down_sync(0xffffffffu, v, o);
    if (lane == 0) red[wid] = v;
    __syncthreads();
    v = (threadIdx.x < 8) ? red[threadIdx.x] : 0.f;
    if (wid == 0) {
        #pragma unroll
        for (int o = 4; o; o >>= 1) v += __shfl_down_sync(0xffffffffu, v, o);
        if (lane == 0) red[0] = v;
    }
    __syncthreads();
    return red[0];
}

__device__ __forceinline__ float softplusf(float x) {
    return (x > 20.f) ? x : log1pf(expf(x));
}
__device__ __forceinline__ float siluf(float x) {
    return x / (1.f + expf(-x));
}
__device__ __forceinline__ unsigned f2tf(float f) {
    unsigned u;
    asm("cvt.rna.tf32.f32 %0, %1;" : "=r"(u) : "f"(f));
    return u;
}
__device__ __forceinline__ float f2tff(float f) { return __uint_as_float(f2tf(f)); }
__device__ __forceinline__ void mma_tf32(float* d, const unsigned* a, const unsigned* b) {
    asm volatile(
        "mma.sync.aligned.m16n8k8.row.col.f32.tf32.tf32.f32 "
        "{%0,%1,%2,%3}, {%4,%5,%6,%7}, {%8,%9}, {%0,%1,%2,%3};"
        : "+f"(d[0]), "+f"(d[1]), "+f"(d[2]), "+f"(d[3])
        : "r"(a[0]), "r"(a[1]), "r"(a[2]), "r"(a[3]), "r"(b[0]), "r"(b[1]));
}

// ---------------- 0) weight pre-round to tf32 ----------------
__global__ __launch_bounds__(256) void k_round(
    const float* __restrict__ in, float* __restrict__ out, int n4)
{
    int i = blockIdx.x * 256 + threadIdx.x;
    if (i < n4) {
        float4 v = ((const float4*)in)[i];
        v.x = f2tff(v.x); v.y = f2tff(v.y); v.z = f2tff(v.z); v.w = f2tff(v.w);
        ((float4*)out)[i] = v;
    }
}

// ---------------- 1) residual add + RMSNorm (tf32-rounded output) ----------------
__global__ __launch_bounds__(256) void k_addnorm(
    const float* __restrict__ hid, const float* __restrict__ resi,
    const float* __restrict__ w, float* __restrict__ resout)
{
    int row = blockIdx.x, t = threadIdx.x;
    size_t off = (size_t)row * DM;
    float4 hv = ((const float4*)(hid + off))[t];
    float4 rv = ((const float4*)(resi + off))[t];
    hv.x += rv.x; hv.y += rv.y; hv.z += rv.z; hv.w += rv.w;
    ((float4*)(resout + off))[t] = hv;
    float s = hv.x*hv.x + hv.y*hv.y + hv.z*hv.z + hv.w*hv.w;
    s = blockReduceSum256(s);
    float sc = rsqrtf(s * (1.0f / DM) + EPSF);
    float4 wv = ((const float4*)w)[t];
    float4 o;
    o.x = f2tff(hv.x * sc * wv.x); o.y = f2tff(hv.y * sc * wv.y);
    o.z = f2tff(hv.z * sc * wv.z); o.w = f2tff(hv.w * sc * wv.w);
    ((float4*)(g_hn + off))[t] = o;
}

// ---------------- 2) TF32 tensor-core GEMM, cp.async double-buffered ----------------
// C[M,N] = A[M,K] @ B[K,N], row-major, inputs pre-rounded to tf32.
// 128x128x16 CTA tile, 256 threads = 8 warps (2x4), warp tile 64x32.
__global__ __launch_bounds__(256, 2) void gemm_tf32(
    const float* __restrict__ A, const float* __restrict__ Bm,
    float* __restrict__ C, int M, int N, int K)
{
    __shared__ unsigned As[2][128 * 20];
    __shared__ unsigned Bs[2][16 * 128];
    int tid = threadIdx.x;
    int lane = tid & 31, warp = tid >> 5;
    int warpRow = warp >> 2, warpCol = warp & 3;
    int rowBase = blockIdx.y * 128, colBase = blockIdx.x * 128;

    int aRow = tid >> 2, aCol = (tid & 3) << 2;
    int bRow = warp;                 // 0..7
    int bCol = lane << 2;            // 0..124
    int gid = lane >> 2, tig = lane & 3;
    int lm_row = lane & 15;
    int lm_koff = (lane >> 4) << 2;

    unsigned asBase = (unsigned)__cvta_generic_to_shared(As);
    unsigned bsBase = (unsigned)__cvta_generic_to_shared(Bs);

    const float* aPtr0 = A + (size_t)(rowBase + aRow) * K + aCol;
    const float* aPtr1 = A + (size_t)(rowBase + aRow + 64) * K + aCol;
    int cc = colBase + bCol;
    const float* bPtr0 = Bm + (size_t)bRow * N + cc;
    const float* bPtr1 = Bm + (size_t)(bRow + 8) * N + cc;
    int bsz = (cc < N) ? 16 : 0;     // zero-fill OOB columns
    int swz = (bRow & 3) << 3;       // same for bRow and bRow+8

    unsigned da0 = asBase + (unsigned)((aRow * 20 + aCol) << 2);
    unsigned da1 = da0 + (64 * 20 << 2);
    unsigned db0 = bsBase + (unsigned)(((bRow * 128) + (bCol ^ swz)) << 2);
    unsigned db1 = bsBase + (unsigned)((((bRow + 8) * 128) + (bCol ^ swz)) << 2);

    int nIter = K >> 4;

    #define ISSUE(st, k0) do {                                                        \
        unsigned aoff = (st) ? (128 * 20 << 2) : 0;                                   \
        unsigned boff = (st) ? (16 * 128 << 2) : 0;                                   \
        asm volatile("cp.async.cg.shared.global [%0], [%1], 16;"                      \
                     :: "r"(da0 + aoff), "l"(aPtr0 + (k0)) : "memory");               \
        asm volatile("cp.async.cg.shared.global [%0], [%1], 16;"                      \
                     :: "r"(da1 + aoff), "l"(aPtr1 + (k0)) : "memory");               \
        asm volatile("cp.async.cg.shared.global [%0], [%1], 16, %2;"                  \
                     :: "r"(db0 + boff), "l"(bPtr0 + (size_t)(k0) * N), "r"(bsz) : "memory"); \
        asm volatile("cp.async.cg.shared.global [%0], [%1], 16, %2;"                  \
                     :: "r"(db1 + boff), "l"(bPtr1 + (size_t)(k0) * N), "r"(bsz) : "memory"); \
        asm volatile("cp.async.commit_group;" ::: "memory");                          \
    } while (0)

    float acc[4][4][4] = {};

    ISSUE(0, 0);
    for (int it = 0; it < nIter; it++) {
        if (it + 1 < nIter) {
            ISSUE((it + 1) & 1, (it + 1) << 4);
            asm volatile("cp.async.wait_group 1;" ::: "memory");
        } else {
            asm volatile("cp.async.wait_group 0;" ::: "memory");
        }
        __syncthreads();
        int st = it & 1;
        unsigned aStage = asBase + (unsigned)(st * (128 * 20) << 2);
        const unsigned* bStage = &Bs[st][0];

        #pragma unroll
        for (int ks = 0; ks < 2; ks++) {
            unsigned a[4][4], b[4][2];
            #pragma unroll
            for (int i = 0; i < 4; i++) {
                int mr = warpRow * 64 + i * 16;
                unsigned addr = aStage + (unsigned)(((mr + lm_row) * 20 + ks * 8 + lm_koff) << 2);
                asm volatile("ldmatrix.sync.aligned.m8n8.x4.shared.b16 {%0,%1,%2,%3}, [%4];"
                    : "=r"(a[i][0]), "=r"(a[i][1]), "=r"(a[i][2]), "=r"(a[i][3])
                    : "r"(addr));
            }
            #pragma unroll
            for (int j = 0; j < 4; j++) {
                int col = ((warpCol * 32 + j * 8 + gid) ^ (tig << 3));
                b[j][0] = bStage[(ks * 8 + tig) * 128 + col];
                b[j][1] = bStage[(ks * 8 + tig + 4) * 128 + col];
            }
            #pragma unroll
            for (int i = 0; i < 4; i++)
                #pragma unroll
                for (int j = 0; j < 4; j++)
                    mma_tf32(acc[i][j], a[i], b[j]);
        }
        __syncthreads();
    }
    #undef ISSUE

    #pragma unroll
    for (int i = 0; i < 4; i++) {
        int r0 = rowBase + warpRow * 64 + i * 16 + gid;
        #pragma unroll
        for (int j = 0; j < 4; j++) {
            int ccj = colBase + warpCol * 32 + j * 8 + tig * 2;
            if (ccj < N) {
                *(float2*)(C + (size_t)r0 * N + ccj)       = make_float2(acc[i][j][0], acc[i][j][1]);
                *(float2*)(C + (size_t)(r0 + 8) * N + ccj) = make_float2(acc[i][j][2], acc[i][j][3]);
            }
        }
    }
}

// ---------------- 3) depthwise causal conv (w=4) + bias + SiLU, sliding window ----------------
__global__ __launch_bounds__(256) void k_conv(
    const float* __restrict__ cw, const float* __restrict__ cb)
{
    int ch = blockIdx.x * 256 + threadIdx.x;   // 0..2303
    int rb = blockIdx.y * 64;                  // 64 rows per block, never straddles batch
    int b = rb >> 12;
    int l0 = rb & 4095;
    float w0 = cw[ch], w1 = cw[NCH + ch], w2 = cw[2 * NCH + ch], w3 = cw[3 * NCH + ch];
    float bias = cb[ch];
    const float* src = g_zx + DIN + ch;
    float x1 = 0.f, x2 = 0.f, x3 = 0.f;        // x[l-1], x[l-2], x[l-3]
    if (l0 >= 1) x1 = src[(size_t)(b * LL + l0 - 1) * NPJ];
    if (l0 >= 2) x2 = src[(size_t)(b * LL + l0 - 2) * NPJ];
    if (l0 >= 3) x3 = src[(size_t)(b * LL + l0 - 3) * NPJ];
    #pragma unroll 4
    for (int i = 0; i < 64; i++) {
        int l = l0 + i;
        float cur = src[(size_t)(b * LL + l) * NPJ];
        float acc = bias + w3 * cur + w2 * x1 + w1 * x2 + w0 * x3;
        g_xBC[(size_t)(b * LL + l) * NCH + ch] = siluf(acc);
        x3 = x2; x2 = x1; x1 = cur;
    }
}

// ---------------- 4) dt = softplus(raw+bias); per-chunk cumsum of dt*A ----------------
__global__ __launch_bounds__(256) void k_dtscan(
    const float* __restrict__ dtb, const float* __restrict__ alog)
{
    int bc = blockIdx.x, h = blockIdx.y, l = threadIdx.x;
    int b = bc >> 4, c = bc & 15;
    int row = b * LL + c * CHK + l;
    float raw = g_zx[(size_t)row * NPJ + DIN + NCH + h] + dtb[h];
    float dt = softplusf(raw);
    g_dt[row * HH + h] = dt;
    float v = -dt * expf(alog[h]);
    __shared__ float sb[CHK];
    sb[l] = v;
    __syncthreads();
    for (int o = 1; o < CHK; o <<= 1) {
        float add = (l >= o) ? sb[l - o] : 0.f;
        __syncthreads();
        sb[l] += add;
        __syncthreads();
    }
    g_Acum[(bc * HH + h) * CHK + l] = sb[l];
    if (l == CHK - 1) g_cdec[bc * HH + h] = expf(sb[l]);
}

// ---------------- 5) ST[s,l] = sum_n B[s,n]*C[l,n] per (b,c) ----------------
__global__ __launch_bounds__(256) void k_S()
{
    int st = blockIdx.x, lt = blockIdx.y, bc = blockIdx.z;
    int b = bc >> 4, c = bc & 15;
    int rowb = b * LL + c * CHK;
    int s0 = st * 64, l0 = lt * 64;
    __shared__ float Bsm[32][68];
    __shared__ float Csm[32][68];
    int t = threadIdx.x;
    int ts = t >> 4, tg = t & 15;
    float acc[4][4] = {};
    for (int kt = 0; kt < 4; kt++) {
        for (int idx = t; idx < 2048; idx += 256) {
            int n = idx & 31, s = idx >> 5;
            Bsm[n][s] = g_xBC[(size_t)(rowb + s0 + s) * NCH + DIN + kt * 32 + n];
            Csm[n][s] = g_xBC[(size_t)(rowb + l0 + s) * NCH + DIN + NSt + kt * 32 + n];
        }
        __syncthreads();
        #pragma unroll
        for (int n = 0; n < 32; n++) {
            float sv[4], lv[4];
            *(float4*)&sv[0] = *(const float4*)&Bsm[n][ts * 4];
            *(float4*)&lv[0] = *(const float4*)&Csm[n][tg * 4];
            #pragma unroll
            for (int i = 0; i < 4; i++)
                #pragma unroll
                for (int j = 0; j < 4; j++)
                    acc[i][j] += sv[i] * lv[j];
        }
        __syncthreads();
    }
    float* out = g_S + (size_t)bc * CHK * CHK;
    #pragma unroll
    for (int i = 0; i < 4; i++) {
        float4 v = make_float4(acc[i][0], acc[i][1], acc[i][2], acc[i][3]);
        *(float4*)&out[(s0 + ts * 4 + i) * CHK + l0 + tg * 4] = v;
    }
}

// ---------------- 6) states[p,n] = sum_l B[l,n]*exp(Alast-Acum[l])*x[l,p]*dt[l] ----------------
__global__ __launch_bounds__(256) void k_states()
{
    int bc = blockIdx.x, h = blockIdx.y;
    int b = bc >> 4, c = bc & 15;
    int rowb = b * LL + c * CHK;
    const float* Ac = g_Acum + (bc * HH + h) * CHK;
    __shared__ float wsm[32];
    __shared__ float Bs[32][128];
    __shared__ float Xs[32][68];
    int t = threadIdx.x;
    int tn = t & 15, tp = t >> 4;
    float acc[4][8] = {};
    float alast = Ac[CHK - 1];
    for (int lt = 0; lt < 8; lt++) {
        if (t < 32) wsm[t] = expf(alast - Ac[lt * 32 + t]);
        __syncthreads();
        for (int idx = t; idx < 4096; idx += 256) {
            int n = idx & 127, ll = idx >> 7;
            Bs[ll][n] = g_xBC[(size_t)(rowb + lt * 32 + ll) * NCH + DIN + n] * wsm[ll];
        }
        for (int idx = t; idx < 2048; idx += 256) {
            int p = idx & 63, ll = idx >> 6;
            int row = rowb + lt * 32 + ll;
            Xs[ll][p] = g_xBC[(size_t)row * NCH + h * PP + p] * g_dt[row * HH + h];
        }
        __syncthreads();
        #pragma unroll
        for (int ll = 0; ll < 32; ll++) {
            float pr[4], nr[8];
            *(float4*)&pr[0] = *(const float4*)&Xs[ll][tp * 4];
            *(float4*)&nr[0] = *(const float4*)&Bs[ll][tn * 8];
            *(float4*)&nr[4] = *(const float4*)&Bs[ll][tn * 8 + 4];
            #pragma unroll
            for (int i = 0; i < 4; i++)
                #pragma unroll
                for (int j = 0; j < 8; j++)
                    acc[i][j] += pr[i] * nr[j];
        }
        __syncthreads();
    }
    float* out = g_states + (size_t)(bc * HH + h) * PP * NSt;
    #pragma unroll
    for (int i = 0; i < 4; i++) {
        int p = tp * 4 + i;
        *(float4*)&out[p * NSt + tn * 8]     = make_float4(acc[i][0], acc[i][1], acc[i][2], acc[i][3]);
        *(float4*)&out[p * NSt + tn * 8 + 4] = make_float4(acc[i][4], acc[i][5], acc[i][6], acc[i][7]);
    }
}

// ---------------- 7) inter-chunk recurrence ----------------
__global__ __launch_bounds__(256) void k_scan()
{
    int tid = blockIdx.x * 256 + threadIdx.x;  // 524288
    int n = tid & 127;
    int p = (tid >> 7) & 63;
    int h = (tid >> 13) & 31;
    int b = tid >> 18;
    float carry = 0.f;
    for (int c = 0; c < NC; c++) {
        int bc = b * NC + c;
        size_t idx = (size_t)(bc * HH + h) * PP * NSt + p * NSt + n;
        float dec = g_cdec[bc * HH + h];
        g_prev[idx] = carry;
        carry = carry * dec + g_states[idx];
    }
}

// ---------------- 8) Y = Y_off + Y_diag + D*x ----------------
__global__ __launch_bounds__(256) void k_Y(const float* __restrict__ Dp)
{
    int bc = blockIdx.x, h = blockIdx.y;
    int b = bc >> 4, c = bc & 15;
    int rowb = b * LL + c * CHK;
    int t = threadIdx.x;
    int tl = t >> 2, tp = t & 3;
    int l0 = tl * 4;

    __shared__ float Asm[CHK];
    __shared__ float buf[32 * 260 + 32 * 68];
    float* Csm = buf;
    float* Psm = buf + 32 * 260;
    float* Xs  = buf;

    const float* Ac = g_Acum + (bc * HH + h) * CHK;
    Asm[t] = Ac[t];
    __syncthreads();
    float al[4];
    #pragma unroll
    for (int i = 0; i < 4; i++) al[i] = Asm[l0 + i];
    float rr[4];
    rr[0] = 1.f;
    #pragma unroll
    for (int i = 1; i < 4; i++) rr[i] = expf(al[i] - al[0]);

    float acc[4][16] = {};
    const float* prevp = g_prev + (size_t)(bc * HH + h) * PP * NSt;

    // ---- Y_off ----
    for (int nt = 0; nt < 4; nt++) {
        for (int idx = t; idx < 8192; idx += 256) {
            int n = idx & 31, l = idx >> 5;
            Csm[n * 260 + l] = g_xBC[(size_t)(rowb + l) * NCH + DIN + NSt + nt * 32 + n];
        }
        for (int idx = t; idx < 2048; idx += 256) {
            int n = idx & 31, p = idx >> 5;
            Psm[n * 68 + p] = prevp[p * NSt + nt * 32 + n];
        }
        __syncthreads();
        #pragma unroll
        for (int n = 0; n < 32; n++) {
            float cl[4], pv[16];
            *(float4*)&cl[0] = *(const float4*)&Csm[n * 260 + l0];
            *(float4*)&pv[0]  = *(const float4*)&Psm[n * 68 + tp * 16];
            *(float4*)&pv[4]  = *(const float4*)&Psm[n * 68 + tp * 16 + 4];
            *(float4*)&pv[8]  = *(const float4*)&Psm[n * 68 + tp * 16 + 8];
            *(float4*)&pv[12] = *(const float4*)&Psm[n * 68 + tp * 16 + 12];
            #pragma unroll
            for (int i = 0; i < 4; i++)
                #pragma unroll
                for (int j = 0; j < 16; j++)
                    acc[i][j] += cl[i] * pv[j];
        }
        __syncthreads();
    }
    #pragma unroll
    for (int i = 0; i < 4; i++) {
        float el = expf(al[i]);
        #pragma unroll
        for (int j = 0; j < 16; j++) acc[i][j] *= el;
    }

    // ---- Y_diag ----
    const float* Sp = g_S + (size_t)bc * CHK * CHK;
    for (int st = 0; st < 4; st++) {
        for (int idx = t; idx < 4096; idx += 256) {
            int p = idx & 63, ss = idx >> 6;
            int row = rowb + st * 64 + ss;
            Xs[ss * 68 + p] = g_xBC[(size_t)row * NCH + h * PP + p] * g_dt[row * HH + h];
        }
        __syncthreads();
        int sEnd = l0 + 1 - st * 64;
        if (sEnd > 64) sEnd = 64;
        int bEnd = l0 + 4 - st * 64;
        if (bEnd > 64) bEnd = 64;
        for (int ss = 0; ss < sEnd; ss++) {
            int s = st * 64 + ss;
            float e0 = expf(al[0] - Asm[s]);
            float sv[4], w[4], xv[16];
            *(float4*)&sv[0] = *(const float4*)&Sp[s * CHK + l0];
            #pragma unroll
            for (int i = 0; i < 4; i++) w[i] = sv[i] * (e0 * rr[i]);
            *(float4*)&xv[0]  = *(const float4*)&Xs[ss * 68 + tp * 16];
            *(float4*)&xv[4]  = *(const float4*)&Xs[ss * 68 + tp * 16 + 4];
            *(float4*)&xv[8]  = *(const float4*)&Xs[ss * 68 + tp * 16 + 8];
            *(float4*)&xv[12] = *(const float4*)&Xs[ss * 68 + tp * 16 + 12];
            #pragma unroll
            for (int i = 0; i < 4; i++)
                #pragma unroll
                for (int j = 0; j < 16; j++)
                    acc[i][j] += w[i] * xv[j];
        }
        for (int ss = (sEnd > 0 ? sEnd : 0); ss < bEnd; ss++) {
            int s = st * 64 + ss;
            float as = Asm[s];
            float sv[4], w[4], xv[16];
            *(float4*)&sv[0] = *(const float4*)&Sp[s * CHK + l0];
            #pragma unroll
            for (int i = 0; i < 4; i++)
                w[i] = (s <= l0 + i) ? sv[i] * expf(al[i] - as) : 0.f;
            *(float4*)&xv[0]  = *(const float4*)&Xs[ss * 68 + tp * 16];
            *(float4*)&xv[4]  = *(const float4*)&Xs[ss * 68 + tp * 16 + 4];
            *(float4*)&xv[8]  = *(const float4*)&Xs[ss * 68 + tp * 16 + 8];
            *(float4*)&xv[12] = *(const float4*)&Xs[ss * 68 + tp * 16 + 12];
            #pragma unroll
            for (int i = 0; i < 4; i++)
                #pragma unroll
                for (int j = 0; j < 16; j++)
                    acc[i][j] += w[i] * xv[j];
        }
        __syncthreads();
    }

    // ---- skip term + store ----
    float dh = Dp[h];
    #pragma unroll
    for (int i = 0; i < 4; i++) {
        int row = rowb + l0 + i;
        const float* xr = g_xBC + (size_t)row * NCH + h * PP + tp * 16;
        float* yr = g_y + (size_t)row * DIN + h * PP + tp * 16;
        #pragma unroll
        for (int j4 = 0; j4 < 4; j4++) {
            float4 xv = *(const float4*)(xr + j4 * 4);
            float4 o;
            o.x = acc[i][j4 * 4 + 0] + dh * xv.x;
            o.y = acc[i][j4 * 4 + 1] + dh * xv.y;
            o.z = acc[i][j4 * 4 + 2] + dh * xv.z;
            o.w = acc[i][j4 * 4 + 3] + dh * xv.w;
            *(float4*)(yr + j4 * 4) = o;
        }
    }
}

// ---------------- 9) gated SiLU + RMSNorm over 2048 (tf32-rounded output) ----------------
__global__ __launch_bounds__(256) void k_gatednorm(const float* __restrict__ gw)
{
    int row = blockIdx.x, t = threadIdx.x;
    size_t yo = (size_t)row * DIN;
    size_t zo = (size_t)row * NPJ;
    float4 vv[2];
    float ssum = 0.f;
    #pragma unroll
    for (int k = 0; k < 2; k++) {
        float4 yv = ((const float4*)(g_y + yo))[k * 256 + t];
        float4 zv = ((const float4*)(g_zx + zo))[k * 256 + t];
        float4 v;
        v.x = yv.x * siluf(zv.x); v.y = yv.y * siluf(zv.y);
        v.z = yv.z * siluf(zv.z); v.w = yv.w * siluf(zv.w);
        vv[k] = v;
        ssum += v.x * v.x + v.y * v.y + v.z * v.z + v.w * v.w;
    }
    ssum = blockReduceSum256(ssum);
    float sc = rsqrtf(ssum * (1.0f / DIN) + EPSF);
    #pragma unroll
    for (int k = 0; k < 2; k++) {
        float4 w = ((const float4*)gw)[k * 256 + t];
        float4 v = vv[k];
        float4 o;
        o.x = f2tff(v.x * sc * w.x); o.y = f2tff(v.y * sc * w.y);
        o.z = f2tff(v.z * sc * w.z); o.w = f2tff(v.w * sc * w.w);
        ((float4*)(g_yn + yo))[k * 256 + t] = o;
    }
}

// ---------------- launch ----------------
extern "C" void kernel_launch(void* const* d_in, const int* in_sizes, int n_in,
                              void* d_out, int out_size)
{
    const float* hid  = (const float*)d_in[0];
    const float* resi = (const float*)d_in[1];
    const float* nw   = (const float*)d_in[2];
    const float* inw  = (const float*)d_in[3];
    const float* cw   = (const float*)d_in[4];
    const float* cb   = (const float*)d_in[5];
    const float* dtb  = (const float*)d_in[6];
    const float* alog = (const float*)d_in[7];
    const float* Dp   = (const float*)d_in[8];
    const float* gw   = (const float*)d_in[9];
    const float* ow   = (const float*)d_in[10];

    float* out    = (float*)d_out;
    float* resout = out + (size_t)ROWS * DM;

    float *p_hn, *p_zx, *p_yn, *p_w1, *p_w2;
    cudaGetSymbolAddress((void**)&p_hn, g_hn);
    cudaGetSymbolAddress((void**)&p_zx, g_zx);
    cudaGetSymbolAddress((void**)&p_yn, g_yn);
    cudaGetSymbolAddress((void**)&p_w1, g_w1);
    cudaGetSymbolAddress((void**)&p_w2, g_w2);

    k_round<<<(DM * NPJ / 4 + 255) / 256, 256>>>(inw, p_w1, DM * NPJ / 4);
    k_round<<<(DIN * DM / 4 + 255) / 256, 256>>>(ow, p_w2, DIN * DM / 4);
    k_addnorm<<<ROWS, 256>>>(hid, resi, nw, resout);
    gemm_tf32<<<dim3((NPJ + 127) / 128, ROWS / 128), 256>>>(p_hn, p_w1, p_zx, ROWS, NPJ, DM);
    k_conv<<<dim3(NCH / 256, ROWS / 64), 256>>>(cw, cb);
    k_dtscan<<<dim3(NBC, HH), 256>>>(dtb, alog);
    k_S<<<dim3(4, 4, NBC), 256>>>();
    k_states<<<dim3(NBC, HH), 256>>>();
    k_scan<<<(BB * HH * PP * NSt) / 256, 256>>>();
    k_Y<<<dim3(NBC, HH), 256>>>(Dp);
    k_gatednorm<<<ROWS, 256>>>(gw);
    gemm_tf32<<<dim3(DM / 128, ROWS / 128), 256>>>(p_yn, p_w2, out, ROWS, DM, DIN);
}

// round 6
// speedup vs baseline: 2.4439x; 1.0867x over previous
#include <cuda_runtime.h>
#include <math.h>

// ---------------- geometry ----------------
#define BB   2
#define LL   4096
#define DM   1024
#define DIN  2048
#define HH   32
#define PP   64
#define NSt  128
#define NCH  2304      // DIN + 2*NSt
#define NPJ  4384      // 2*DIN + 2*NSt + HH
#define CHK  256
#define NC   16        // chunks per batch
#define ROWS 8192      // BB*LL
#define NBC  32        // BB*NC
#define EPSF 1e-5f

// ---------------- scratch (static device memory, alloc-free) ----------------
__device__ float g_hn[(size_t)ROWS * DM];        // normalized input (tf32-rounded)
__device__ float g_zx[(size_t)ROWS * NPJ];       // in_proj output
__device__ float g_xBC[(size_t)ROWS * NCH];      // conv+silu output (x | B | C)
__device__ float g_dt[ROWS * HH];                // softplus(dt)
__device__ float g_Acum[NBC * HH * CHK];         // per-chunk inclusive cumsum of dt*A
__device__ float g_cdec[NBC * HH];               // exp(Acum[last]) per (bc,h)
__device__ float g_S[(size_t)NBC * CHK * CHK];   // ST[s*256+l] per (b,c)
__device__ float g_states[(size_t)NBC * HH * PP * NSt];
__device__ float g_prev[(size_t)NBC * HH * PP * NSt];
__device__ float g_y[(size_t)ROWS * DIN];
__device__ float g_yn[(size_t)ROWS * DIN];       // (tf32-rounded)
__device__ float g_w1[(size_t)DM * NPJ];         // tf32-rounded in_proj_w
__device__ float g_w2[(size_t)DIN * DM];         // tf32-rounded out_proj_w

// ---------------- helpers ----------------
__device__ __forceinline__ float blockReduceSum256(float v) {
    __shared__ float red[32];
    int lane = threadIdx.x & 31, wid = threadIdx.x >> 5;
    #pragma unroll
    for (int o = 16; o; o >>= 1) v += __shfl_down_sync(0xffffffffu, v, o);
    if (lane == 0) red[wid] = v;
    __syncthreads();
    v = (threadIdx.x < 8) ? red[threadIdx.x] : 0.f;
    if (wid == 0) {
        #pragma unroll
        for (int o = 4; o; o >>= 1) v += __shfl_down_sync(0xffffffffu, v, o);
        if (lane == 0) red[0] = v;
    }
    __syncthreads();
    return red[0];
}

__device__ __forceinline__ float softplusf(float x) {
    return (x > 20.f) ? x : log1pf(expf(x));
}
__device__ __forceinline__ float siluf(float x) {
    return x / (1.f + expf(-x));
}
__device__ __forceinline__ unsigned f2tf(float f) {
    unsigned u;
    asm("cvt.rna.tf32.f32 %0, %1;" : "=r"(u) : "f"(f));
    return u;
}
__device__ __forceinline__ float f2tff(float f) { return __uint_as_float(f2tf(f)); }
__device__ __forceinline__ void mma_tf32(float* d, const unsigned* a, const unsigned* b) {
    asm volatile(
        "mma.sync.aligned.m16n8k8.row.col.f32.tf32.tf32.f32 "
        "{%0,%1,%2,%3}, {%4,%5,%6,%7}, {%8,%9}, {%0,%1,%2,%3};"
        : "+f"(d[0]), "+f"(d[1]), "+f"(d[2]), "+f"(d[3])
        : "r"(a[0]), "r"(a[1]), "r"(a[2]), "r"(a[3]), "r"(b[0]), "r"(b[1]));
}

// ---------------- 0) weight pre-round to tf32 ----------------
__global__ __launch_bounds__(256) void k_round(
    const float* __restrict__ in, float* __restrict__ out, int n4)
{
    int i = blockIdx.x * 256 + threadIdx.x;
    if (i < n4) {
        float4 v = ((const float4*)in)[i];
        v.x = f2tff(v.x); v.y = f2tff(v.y); v.z = f2tff(v.z); v.w = f2tff(v.w);
        ((float4*)out)[i] = v;
    }
}

// ---------------- 1) residual add + RMSNorm (tf32-rounded output) ----------------
__global__ __launch_bounds__(256) void k_addnorm(
    const float* __restrict__ hid, const float* __restrict__ resi,
    const float* __restrict__ w, float* __restrict__ resout)
{
    int row = blockIdx.x, t = threadIdx.x;
    size_t off = (size_t)row * DM;
    float4 hv = ((const float4*)(hid + off))[t];
    float4 rv = ((const float4*)(resi + off))[t];
    hv.x += rv.x; hv.y += rv.y; hv.z += rv.z; hv.w += rv.w;
    ((float4*)(resout + off))[t] = hv;
    float s = hv.x*hv.x + hv.y*hv.y + hv.z*hv.z + hv.w*hv.w;
    s = blockReduceSum256(s);
    float sc = rsqrtf(s * (1.0f / DM) + EPSF);
    float4 wv = ((const float4*)w)[t];
    float4 o;
    o.x = f2tff(hv.x * sc * wv.x); o.y = f2tff(hv.y * sc * wv.y);
    o.z = f2tff(hv.z * sc * wv.z); o.w = f2tff(hv.w * sc * wv.w);
    ((float4*)(g_hn + off))[t] = o;
}

// ---------------- 2) TF32 tensor-core GEMM, 3-stage cp.async, 1 sync/iter ----------------
// C[M,N] = A[M,K] @ B[K,N], row-major, inputs pre-rounded to tf32.
// 128x128x16 CTA tile, 256 threads = 8 warps (2x4), warp tile 64x32.
#define AS_WORDS (128 * 20)
#define BS_WORDS (16 * 128)
#define GEMM_SMEM (3 * (AS_WORDS + BS_WORDS) * 4)
__global__ __launch_bounds__(256, 2) void gemm_tf32(
    const float* __restrict__ A, const float* __restrict__ Bm,
    float* __restrict__ C, int M, int N, int K)
{
    extern __shared__ unsigned smemBuf[];
    unsigned* AsBase = smemBuf;                   // 3 stages of AS_WORDS
    unsigned* BsBase = smemBuf + 3 * AS_WORDS;    // 3 stages of BS_WORDS

    int tid = threadIdx.x;
    int lane = tid & 31, warp = tid >> 5;
    int warpRow = warp >> 2, warpCol = warp & 3;
    int rowBase = blockIdx.y * 128, colBase = blockIdx.x * 128;

    int aRow = tid >> 2, aCol = (tid & 3) << 2;
    int bRow = warp;                 // 0..7
    int bCol = lane << 2;            // 0..124
    int gid = lane >> 2, tig = lane & 3;
    int lm_row = lane & 15;
    int lm_koff = (lane >> 4) << 2;

    unsigned asBase = (unsigned)__cvta_generic_to_shared(AsBase);
    unsigned bsBase = (unsigned)__cvta_generic_to_shared(BsBase);

    const float* aPtr0 = A + (size_t)(rowBase + aRow) * K + aCol;
    const float* aPtr1 = A + (size_t)(rowBase + aRow + 64) * K + aCol;
    int cc = colBase + bCol;
    const float* bPtr0 = Bm + (size_t)bRow * N + cc;
    const float* bPtr1 = Bm + (size_t)(bRow + 8) * N + cc;
    int bsz = (cc < N) ? 16 : 0;     // zero-fill OOB columns
    int swz = (bRow & 3) << 3;       // same for bRow and bRow+8

    unsigned da0 = asBase + (unsigned)((aRow * 20 + aCol) << 2);
    unsigned da1 = da0 + (64 * 20 << 2);
    unsigned db0 = bsBase + (unsigned)(((bRow * 128) + (bCol ^ swz)) << 2);
    unsigned db1 = bsBase + (unsigned)((((bRow + 8) * 128) + (bCol ^ swz)) << 2);

    int nIter = K >> 4;

    #define ISSUE(st, k0) do {                                                        \
        unsigned aoff = (unsigned)(st) * (AS_WORDS << 2);                             \
        unsigned boff = (unsigned)(st) * (BS_WORDS << 2);                             \
        asm volatile("cp.async.cg.shared.global [%0], [%1], 16;"                      \
                     :: "r"(da0 + aoff), "l"(aPtr0 + (k0)) : "memory");               \
        asm volatile("cp.async.cg.shared.global [%0], [%1], 16;"                      \
                     :: "r"(da1 + aoff), "l"(aPtr1 + (k0)) : "memory");               \
        asm volatile("cp.async.cg.shared.global [%0], [%1], 16, %2;"                  \
                     :: "r"(db0 + boff), "l"(bPtr0 + (size_t)(k0) * N), "r"(bsz) : "memory"); \
        asm volatile("cp.async.cg.shared.global [%0], [%1], 16, %2;"                  \
                     :: "r"(db1 + boff), "l"(bPtr1 + (size_t)(k0) * N), "r"(bsz) : "memory"); \
        asm volatile("cp.async.commit_group;" ::: "memory");                          \
    } while (0)

    float acc[4][4][4] = {};

    ISSUE(0, 0);
    if (nIter > 1) ISSUE(1, 16);

    int st = 0;
    for (int it = 0; it < nIter; it++) {
        if (it + 1 < nIter)
            asm volatile("cp.async.wait_group 1;" ::: "memory");
        else
            asm volatile("cp.async.wait_group 0;" ::: "memory");
        __syncthreads();
        if (it + 2 < nIter) {
            int stN = st + 2; if (stN >= 3) stN -= 3;
            ISSUE(stN, (it + 2) << 4);
        }

        unsigned aStage = asBase + (unsigned)(st * (AS_WORDS << 2));
        const unsigned* bStage = BsBase + st * BS_WORDS;

        #pragma unroll
        for (int ks = 0; ks < 2; ks++) {
            unsigned a[4][4], b[4][2];
            #pragma unroll
            for (int i = 0; i < 4; i++) {
                int mr = warpRow * 64 + i * 16;
                unsigned addr = aStage + (unsigned)(((mr + lm_row) * 20 + ks * 8 + lm_koff) << 2);
                asm volatile("ldmatrix.sync.aligned.m8n8.x4.shared.b16 {%0,%1,%2,%3}, [%4];"
                    : "=r"(a[i][0]), "=r"(a[i][1]), "=r"(a[i][2]), "=r"(a[i][3])
                    : "r"(addr));
            }
            #pragma unroll
            for (int j = 0; j < 4; j++) {
                int col = ((warpCol * 32 + j * 8 + gid) ^ (tig << 3));
                b[j][0] = bStage[(ks * 8 + tig) * 128 + col];
                b[j][1] = bStage[(ks * 8 + tig + 4) * 128 + col];
            }
            #pragma unroll
            for (int i = 0; i < 4; i++)
                #pragma unroll
                for (int j = 0; j < 4; j++)
                    mma_tf32(acc[i][j], a[i], b[j]);
        }
        st++; if (st >= 3) st -= 3;
    }
    #undef ISSUE

    #pragma unroll
    for (int i = 0; i < 4; i++) {
        int r0 = rowBase + warpRow * 64 + i * 16 + gid;
        #pragma unroll
        for (int j = 0; j < 4; j++) {
            int ccj = colBase + warpCol * 32 + j * 8 + tig * 2;
            if (ccj < N) {
                *(float2*)(C + (size_t)r0 * N + ccj)       = make_float2(acc[i][j][0], acc[i][j][1]);
                *(float2*)(C + (size_t)(r0 + 8) * N + ccj) = make_float2(acc[i][j][2], acc[i][j][3]);
            }
        }
    }
}

// ---------------- 3) depthwise causal conv (w=4) + bias + SiLU, sliding window ----------------
__global__ __launch_bounds__(256) void k_conv(
    const float* __restrict__ cw, const float* __restrict__ cb)
{
    int ch = blockIdx.x * 256 + threadIdx.x;   // 0..2303
    int rb = blockIdx.y * 64;                  // 64 rows per block, never straddles batch
    int b = rb >> 12;
    int l0 = rb & 4095;
    float w0 = cw[ch], w1 = cw[NCH + ch], w2 = cw[2 * NCH + ch], w3 = cw[3 * NCH + ch];
    float bias = cb[ch];
    const float* src = g_zx + DIN + ch;
    float x1 = 0.f, x2 = 0.f, x3 = 0.f;
    if (l0 >= 1) x1 = src[(size_t)(b * LL + l0 - 1) * NPJ];
    if (l0 >= 2) x2 = src[(size_t)(b * LL + l0 - 2) * NPJ];
    if (l0 >= 3) x3 = src[(size_t)(b * LL + l0 - 3) * NPJ];
    #pragma unroll 4
    for (int i = 0; i < 64; i++) {
        int l = l0 + i;
        float cur = src[(size_t)(b * LL + l) * NPJ];
        float acc = bias + w3 * cur + w2 * x1 + w1 * x2 + w0 * x3;
        g_xBC[(size_t)(b * LL + l) * NCH + ch] = siluf(acc);
        x3 = x2; x2 = x1; x1 = cur;
    }
}

// ---------------- 4) dt = softplus(raw+bias); per-chunk cumsum of dt*A ----------------
__global__ __launch_bounds__(256) void k_dtscan(
    const float* __restrict__ dtb, const float* __restrict__ alog)
{
    int bc = blockIdx.x, h = blockIdx.y, l = threadIdx.x;
    int b = bc >> 4, c = bc & 15;
    int row = b * LL + c * CHK + l;
    float raw = g_zx[(size_t)row * NPJ + DIN + NCH + h] + dtb[h];
    float dt = softplusf(raw);
    g_dt[row * HH + h] = dt;
    float v = -dt * expf(alog[h]);
    __shared__ float sb[CHK];
    sb[l] = v;
    __syncthreads();
    for (int o = 1; o < CHK; o <<= 1) {
        float add = (l >= o) ? sb[l - o] : 0.f;
        __syncthreads();
        sb[l] += add;
        __syncthreads();
    }
    g_Acum[(bc * HH + h) * CHK + l] = sb[l];
    if (l == CHK - 1) g_cdec[bc * HH + h] = expf(sb[l]);
}

// ---------------- 5) ST[s,l] = sum_n B[s,n]*C[l,n] per (b,c) ----------------
__global__ __launch_bounds__(256) void k_S()
{
    int st = blockIdx.x, lt = blockIdx.y, bc = blockIdx.z;
    int b = bc >> 4, c = bc & 15;
    int rowb = b * LL + c * CHK;
    int s0 = st * 64, l0 = lt * 64;
    __shared__ float Bsm[32][68];
    __shared__ float Csm[32][68];
    int t = threadIdx.x;
    int ts = t >> 4, tg = t & 15;
    float acc[4][4] = {};
    for (int kt = 0; kt < 4; kt++) {
        for (int idx = t; idx < 2048; idx += 256) {
            int n = idx & 31, s = idx >> 5;
            Bsm[n][s] = g_xBC[(size_t)(rowb + s0 + s) * NCH + DIN + kt * 32 + n];
            Csm[n][s] = g_xBC[(size_t)(rowb + l0 + s) * NCH + DIN + NSt + kt * 32 + n];
        }
        __syncthreads();
        #pragma unroll
        for (int n = 0; n < 32; n++) {
            float sv[4], lv[4];
            *(float4*)&sv[0] = *(const float4*)&Bsm[n][ts * 4];
            *(float4*)&lv[0] = *(const float4*)&Csm[n][tg * 4];
            #pragma unroll
            for (int i = 0; i < 4; i++)
                #pragma unroll
                for (int j = 0; j < 4; j++)
                    acc[i][j] += sv[i] * lv[j];
        }
        __syncthreads();
    }
    float* out = g_S + (size_t)bc * CHK * CHK;
    #pragma unroll
    for (int i = 0; i < 4; i++) {
        float4 v = make_float4(acc[i][0], acc[i][1], acc[i][2], acc[i][3]);
        *(float4*)&out[(s0 + ts * 4 + i) * CHK + l0 + tg * 4] = v;
    }
}

// ---------------- 6) states[p,n] = sum_l B[l,n]*exp(Alast-Acum[l])*x[l,p]*dt[l] ----------------
__global__ __launch_bounds__(256) void k_states()
{
    int bc = blockIdx.x, h = blockIdx.y;
    int b = bc >> 4, c = bc & 15;
    int rowb = b * LL + c * CHK;
    const float* Ac = g_Acum + (bc * HH + h) * CHK;
    __shared__ float wsm[32];
    __shared__ float Bs[32][128];
    __shared__ float Xs[32][68];
    int t = threadIdx.x;
    int tn = t & 15, tp = t >> 4;
    float acc[4][8] = {};
    float alast = Ac[CHK - 1];
    for (int lt = 0; lt < 8; lt++) {
        if (t < 32) wsm[t] = expf(alast - Ac[lt * 32 + t]);
        __syncthreads();
        for (int idx = t; idx < 4096; idx += 256) {
            int n = idx & 127, ll = idx >> 7;
            Bs[ll][n] = g_xBC[(size_t)(rowb + lt * 32 + ll) * NCH + DIN + n] * wsm[ll];
        }
        for (int idx = t; idx < 2048; idx += 256) {
            int p = idx & 63, ll = idx >> 6;
            int row = rowb + lt * 32 + ll;
            Xs[ll][p] = g_xBC[(size_t)row * NCH + h * PP + p] * g_dt[row * HH + h];
        }
        __syncthreads();
        #pragma unroll
        for (int ll = 0; ll < 32; ll++) {
            float pr[4], nr[8];
            *(float4*)&pr[0] = *(const float4*)&Xs[ll][tp * 4];
            *(float4*)&nr[0] = *(const float4*)&Bs[ll][tn * 8];
            *(float4*)&nr[4] = *(const float4*)&Bs[ll][tn * 8 + 4];
            #pragma unroll
            for (int i = 0; i < 4; i++)
                #pragma unroll
                for (int j = 0; j < 8; j++)
                    acc[i][j] += pr[i] * nr[j];
        }
        __syncthreads();
    }
    float* out = g_states + (size_t)(bc * HH + h) * PP * NSt;
    #pragma unroll
    for (int i = 0; i < 4; i++) {
        int p = tp * 4 + i;
        *(float4*)&out[p * NSt + tn * 8]     = make_float4(acc[i][0], acc[i][1], acc[i][2], acc[i][3]);
        *(float4*)&out[p * NSt + tn * 8 + 4] = make_float4(acc[i][4], acc[i][5], acc[i][6], acc[i][7]);
    }
}

// ---------------- 7) inter-chunk recurrence ----------------
__global__ __launch_bounds__(256) void k_scan()
{
    int tid = blockIdx.x * 256 + threadIdx.x;  // 524288
    int n = tid & 127;
    int p = (tid >> 7) & 63;
    int h = (tid >> 13) & 31;
    int b = tid >> 18;
    float carry = 0.f;
    for (int c = 0; c < NC; c++) {
        int bc = b * NC + c;
        size_t idx = (size_t)(bc * HH + h) * PP * NSt + p * NSt + n;
        float dec = g_cdec[bc * HH + h];
        g_prev[idx] = carry;
        carry = carry * dec + g_states[idx];
    }
}

// ---------------- 8) Y = Y_off + Y_diag + D*x ----------------
__global__ __launch_bounds__(256) void k_Y(const float* __restrict__ Dp)
{
    int bc = blockIdx.x, h = blockIdx.y;
    int b = bc >> 4, c = bc & 15;
    int rowb = b * LL + c * CHK;
    int t = threadIdx.x;
    int tl = t >> 2, tp = t & 3;
    int l0 = tl * 4;

    __shared__ float Asm[CHK];
    __shared__ float buf[10496];
    float* Csm = buf;                // 32*260 = 8320
    float* Psm = buf + 8320;         // 32*68  = 2176  (off phase: 10496 total)
    float* Xs2 = buf;                // 32*68  = 2176  (diag phase)
    float* Ssm = buf + 2176;         // 32*260 = 8320  (diag phase)

    const float* Ac = g_Acum + (bc * HH + h) * CHK;
    Asm[t] = Ac[t];
    __syncthreads();
    float al[4];
    #pragma unroll
    for (int i = 0; i < 4; i++) al[i] = Asm[l0 + i];
    float rr[4];
    rr[0] = 1.f;
    #pragma unroll
    for (int i = 1; i < 4; i++) rr[i] = expf(al[i] - al[0]);

    float acc[4][16] = {};
    const float* prevp = g_prev + (size_t)(bc * HH + h) * PP * NSt;

    // ---- Y_off: acc[l,p] = sum_n C[l,n] * prev[p,n] ----
    for (int nt = 0; nt < 4; nt++) {
        for (int idx = t; idx < 8192; idx += 256) {
            int n = idx & 31, l = idx >> 5;
            Csm[n * 260 + l] = g_xBC[(size_t)(rowb + l) * NCH + DIN + NSt + nt * 32 + n];
        }
        for (int idx = t; idx < 2048; idx += 256) {
            int n = idx & 31, p = idx >> 5;
            Psm[n * 68 + p] = prevp[p * NSt + nt * 32 + n];
        }
        __syncthreads();
        #pragma unroll
        for (int n = 0; n < 32; n++) {
            float cl[4], pv[16];
            *(float4*)&cl[0] = *(const float4*)&Csm[n * 260 + l0];
            *(float4*)&pv[0]  = *(const float4*)&Psm[n * 68 + tp * 16];
            *(float4*)&pv[4]  = *(const float4*)&Psm[n * 68 + tp * 16 + 4];
            *(float4*)&pv[8]  = *(const float4*)&Psm[n * 68 + tp * 16 + 8];
            *(float4*)&pv[12] = *(const float4*)&Psm[n * 68 + tp * 16 + 12];
            #pragma unroll
            for (int i = 0; i < 4; i++)
                #pragma unroll
                for (int j = 0; j < 16; j++)
                    acc[i][j] += cl[i] * pv[j];
        }
        __syncthreads();
    }
    #pragma unroll
    for (int i = 0; i < 4; i++) {
        float el = expf(al[i]);
        #pragma unroll
        for (int j = 0; j < 16; j++) acc[i][j] *= el;
    }

    // ---- Y_diag: acc[l,p] += sum_{s<=l} ST[s,l]*exp(Acum[l]-Acum[s])*xdt[s,p] ----
    // 8 tiles of 32 s-rows; S and Xdt staged in smem (coalesced once).
    const float* Sp = g_S + (size_t)bc * CHK * CHK;
    for (int st8 = 0; st8 < 8; st8++) {
        int s0 = st8 * 32;
        for (int idx = t; idx < 2048; idx += 256) {
            int p = idx & 63, ss = idx >> 6;
            int row = rowb + s0 + ss;
            Xs2[ss * 68 + p] = g_xBC[(size_t)row * NCH + h * PP + p] * g_dt[row * HH + h];
        }
        for (int idx = t; idx < 2048; idx += 256) {   // 32 rows x 64 float4
            int c4 = idx & 63, ss = idx >> 6;
            *(float4*)&Ssm[ss * 260 + c4 * 4] = *(const float4*)&Sp[(s0 + ss) * CHK + c4 * 4];
        }
        __syncthreads();
        int sEnd = l0 + 1 - s0; if (sEnd > 32) sEnd = 32;
        int bEnd = l0 + 4 - s0; if (bEnd > 32) bEnd = 32;
        for (int ss = 0; ss < sEnd; ss++) {
            int s = s0 + ss;
            float e0 = expf(al[0] - Asm[s]);
            float sv[4], w[4], xv[16];
            *(float4*)&sv[0] = *(const float4*)&Ssm[ss * 260 + l0];
            #pragma unroll
            for (int i = 0; i < 4; i++) w[i] = sv[i] * (e0 * rr[i]);
            *(float4*)&xv[0]  = *(const float4*)&Xs2[ss * 68 + tp * 16];
            *(float4*)&xv[4]  = *(const float4*)&Xs2[ss * 68 + tp * 16 + 4];
            *(float4*)&xv[8]  = *(const float4*)&Xs2[ss * 68 + tp * 16 + 8];
            *(float4*)&xv[12] = *(const float4*)&Xs2[ss * 68 + tp * 16 + 12];
            #pragma unroll
            for (int i = 0; i < 4; i++)
                #pragma unroll
                for (int j = 0; j < 16; j++)
                    acc[i][j] += w[i] * xv[j];
        }
        for (int ss = (sEnd > 0 ? sEnd : 0); ss < bEnd; ss++) {
            int s = s0 + ss;
            float as = Asm[s];
            float sv[4], w[4], xv[16];
            *(float4*)&sv[0] = *(const float4*)&Ssm[ss * 260 + l0];
            #pragma unroll
            for (int i = 0; i < 4; i++)
                w[i] = (s <= l0 + i) ? sv[i] * expf(al[i] - as) : 0.f;
            *(float4*)&xv[0]  = *(const float4*)&Xs2[ss * 68 + tp * 16];
            *(float4*)&xv[4]  = *(const float4*)&Xs2[ss * 68 + tp * 16 + 4];
            *(float4*)&xv[8]  = *(const float4*)&Xs2[ss * 68 + tp * 16 + 8];
            *(float4*)&xv[12] = *(const float4*)&Xs2[ss * 68 + tp * 16 + 12];
            #pragma unroll
            for (int i = 0; i < 4; i++)
                #pragma unroll
                for (int j = 0; j < 16; j++)
                    acc[i][j] += w[i] * xv[j];
        }
        __syncthreads();
    }

    // ---- skip term + store ----
    float dh = Dp[h];
    #pragma unroll
    for (int i = 0; i < 4; i++) {
        int row = rowb + l0 + i;
        const float* xr = g_xBC + (size_t)row * NCH + h * PP + tp * 16;
        float* yr = g_y + (size_t)row * DIN + h * PP + tp * 16;
        #pragma unroll
        for (int j4 = 0; j4 < 4; j4++) {
            float4 xv = *(const float4*)(xr + j4 * 4);
            float4 o;
            o.x = acc[i][j4 * 4 + 0] + dh * xv.x;
            o.y = acc[i][j4 * 4 + 1] + dh * xv.y;
            o.z = acc[i][j4 * 4 + 2] + dh * xv.z;
            o.w = acc[i][j4 * 4 + 3] + dh * xv.w;
            *(float4*)(yr + j4 * 4) = o;
        }
    }
}

// ---------------- 9) gated SiLU + RMSNorm over 2048 (tf32-rounded output) ----------------
__global__ __launch_bounds__(256) void k_gatednorm(const float* __restrict__ gw)
{
    int row = blockIdx.x, t = threadIdx.x;
    size_t yo = (size_t)row * DIN;
    size_t zo = (size_t)row * NPJ;
    float4 vv[2];
    float ssum = 0.f;
    #pragma unroll
    for (int k = 0; k < 2; k++) {
        float4 yv = ((const float4*)(g_y + yo))[k * 256 + t];
        float4 zv = ((const float4*)(g_zx + zo))[k * 256 + t];
        float4 v;
        v.x = yv.x * siluf(zv.x); v.y = yv.y * siluf(zv.y);
        v.z = yv.z * siluf(zv.z); v.w = yv.w * siluf(zv.w);
        vv[k] = v;
        ssum += v.x * v.x + v.y * v.y + v.z * v.z + v.w * v.w;
    }
    ssum = blockReduceSum256(ssum);
    float sc = rsqrtf(ssum * (1.0f / DIN) + EPSF);
    #pragma unroll
    for (int k = 0; k < 2; k++) {
        float4 w = ((const float4*)gw)[k * 256 + t];
        float4 v = vv[k];
        float4 o;
        o.x = f2tff(v.x * sc * w.x); o.y = f2tff(v.y * sc * w.y);
        o.z = f2tff(v.z * sc * w.z); o.w = f2tff(v.w * sc * w.w);
        ((float4*)(g_yn + yo))[k * 256 + t] = o;
    }
}

// ---------------- launch ----------------
extern "C" void kernel_launch(void* const* d_in, const int* in_sizes, int n_in,
                              void* d_out, int out_size)
{
    const float* hid  = (const float*)d_in[0];
    const float* resi = (const float*)d_in[1];
    const float* nw   = (const float*)d_in[2];
    const float* inw  = (const float*)d_in[3];
    const float* cw   = (const float*)d_in[4];
    const float* cb   = (const float*)d_in[5];
    const float* dtb  = (const float*)d_in[6];
    const float* alog = (const float*)d_in[7];
    const float* Dp   = (const float*)d_in[8];
    const float* gw   = (const float*)d_in[9];
    const float* ow   = (const float*)d_in[10];

    float* out    = (float*)d_out;
    float* resout = out + (size_t)ROWS * DM;

    float *p_hn, *p_zx, *p_yn, *p_w1, *p_w2;
    cudaGetSymbolAddress((void**)&p_hn, g_hn);
    cudaGetSymbolAddress((void**)&p_zx, g_zx);
    cudaGetSymbolAddress((void**)&p_yn, g_yn);
    cudaGetSymbolAddress((void**)&p_w1, g_w1);
    cudaGetSymbolAddress((void**)&p_w2, g_w2);

    cudaFuncSetAttribute(gemm_tf32, cudaFuncAttributeMaxDynamicSharedMemorySize, GEMM_SMEM);

    k_round<<<(DM * NPJ / 4 + 255) / 256, 256>>>(inw, p_w1, DM * NPJ / 4);
    k_round<<<(DIN * DM / 4 + 255) / 256, 256>>>(ow, p_w2, DIN * DM / 4);
    k_addnorm<<<ROWS, 256>>>(hid, resi, nw, resout);
    gemm_tf32<<<dim3((NPJ + 127) / 128, ROWS / 128), 256, GEMM_SMEM>>>(p_hn, p_w1, p_zx, ROWS, NPJ, DM);
    k_conv<<<dim3(NCH / 256, ROWS / 64), 256>>>(cw, cb);
    k_dtscan<<<dim3(NBC, HH), 256>>>(dtb, alog);
    k_S<<<dim3(4, 4, NBC), 256>>>();
    k_states<<<dim3(NBC, HH), 256>>>();
    k_scan<<<(BB * HH * PP * NSt) / 256, 256>>>();
    k_Y<<<dim3(NBC, HH), 256>>>(Dp);
    k_gatednorm<<<ROWS, 256>>>(gw);
    gemm_tf32<<<dim3(DM / 128, ROWS / 128), 256, GEMM_SMEM>>>(p_yn, p_w2, out, ROWS, DM, DIN);
}